// round 1
// baseline (speedup 1.0000x reference)
#include <cuda_runtime.h>
#include <math.h>
#include <float.h>

// Problem-fixed shapes (from setup_inputs): z [B,D], W [C,D], out [B,C]
#define Bq 4096
#define Dq 2048
#define Cq 1000
#define Nsup (Bq + Cq)   // 5096 supports
#define KMAX 128
#define NTHR 256

// ---------------- scratch (static device globals; no allocation) ----------------
__device__ float g_Pw[Cq * Cq];        // 4 MB   W @ W^T
__device__ float g_Pz[Bq * Cq];        // 16 MB  z @ W^T
__device__ float g_ent[Nsup];
__device__ int   g_yhat[Nsup];
__device__ float g_invn[Nsup];
__device__ int   g_selidx[Cq * KMAX];
__device__ int   g_selcnt[Cq];
__device__ float g_wT[Cq * Dq];        // 8 MB   weights transposed: row c = prototype c

// ---------------- NT SGEMM: C[M,N] = A[M,K] * B[N,K]^T, row-major, K % 16 == 0 ----
#define BM 128
#define BN 64
#define BK 16
#define TM 8
#define TN 4

__global__ __launch_bounds__(NTHR) void gemm_nt(
    const float* __restrict__ A, const float* __restrict__ B,
    float* __restrict__ C, int M, int N, int K)
{
    __shared__ float As[BK][BM + 4];
    __shared__ float Bs[BK][BN + 4];

    const int tid = threadIdx.x;
    const int tx = tid & 15;     // 0..15 -> col group (TN each)
    const int ty = tid >> 4;     // 0..15 -> row group (TM each)
    const int rowBase = blockIdx.y * BM;
    const int colBase = blockIdx.x * BN;

    float acc[TM][TN];
#pragma unroll
    for (int i = 0; i < TM; i++)
#pragma unroll
        for (int j = 0; j < TN; j++) acc[i][j] = 0.f;

    for (int k0 = 0; k0 < K; k0 += BK) {
        // A tile: BM x BK = 512 float4, 2 per thread
#pragma unroll
        for (int l = 0; l < 2; l++) {
            int idx = tid + l * NTHR;       // 0..511
            int r = idx >> 2;               // 0..127
            int s = idx & 3;                // float4 segment in k
            int grow = rowBase + r;
            float4 v = make_float4(0.f, 0.f, 0.f, 0.f);
            if (grow < M) v = *(const float4*)&A[(size_t)grow * K + k0 + s * 4];
            As[s * 4 + 0][r] = v.x; As[s * 4 + 1][r] = v.y;
            As[s * 4 + 2][r] = v.z; As[s * 4 + 3][r] = v.w;
        }
        // B tile: BN x BK = 256 float4, 1 per thread
        {
            int r = tid >> 2;
            int s = tid & 3;
            int grow = colBase + r;
            float4 v = make_float4(0.f, 0.f, 0.f, 0.f);
            if (grow < N) v = *(const float4*)&B[(size_t)grow * K + k0 + s * 4];
            Bs[s * 4 + 0][r] = v.x; Bs[s * 4 + 1][r] = v.y;
            Bs[s * 4 + 2][r] = v.z; Bs[s * 4 + 3][r] = v.w;
        }
        __syncthreads();

#pragma unroll
        for (int kk = 0; kk < BK; kk++) {
            float a[TM], b[TN];
#pragma unroll
            for (int i = 0; i < TM; i++) a[i] = As[kk][ty * TM + i];
#pragma unroll
            for (int j = 0; j < TN; j++) b[j] = Bs[kk][tx * TN + j];
#pragma unroll
            for (int i = 0; i < TM; i++)
#pragma unroll
                for (int j = 0; j < TN; j++) acc[i][j] += a[i] * b[j];
        }
        __syncthreads();
    }

#pragma unroll
    for (int i = 0; i < TM; i++) {
        int r = rowBase + ty * TM + i;
        if (r >= M) continue;
#pragma unroll
        for (int j = 0; j < TN; j++) {
            int c = colBase + tx * TN + j;
            if (c < N) C[(size_t)r * N + c] = acc[i][j];
        }
    }
}

// ------------- per-row entropy (natural log, stable) + argmax (first max) -------
__global__ __launch_bounds__(NTHR) void row_entropy_argmax(
    const float* __restrict__ P, int ncols,
    float* __restrict__ ent, int* __restrict__ yhat)
{
    const int row = blockIdx.x;
    const float* p = P + (size_t)row * ncols;
    const int tid = threadIdx.x;

    __shared__ float sm[NTHR];
    __shared__ int   si[NTHR];

    // pass 1: max + argmax (first index on ties)
    float m = -FLT_MAX; int mi = 0x7fffffff;
    for (int c = tid; c < ncols; c += NTHR) {
        float v = p[c];
        if (v > m) { m = v; mi = c; }
    }
    sm[tid] = m; si[tid] = mi;
    __syncthreads();
    for (int s = NTHR / 2; s > 0; s >>= 1) {
        if (tid < s) {
            float m2 = sm[tid + s]; int i2 = si[tid + s];
            if (m2 > sm[tid] || (m2 == sm[tid] && i2 < si[tid])) { sm[tid] = m2; si[tid] = i2; }
        }
        __syncthreads();
    }
    const float rowmax = sm[0];
    const int rowarg = si[0];
    __syncthreads();

    // pass 2: s1 = sum exp(v-m), s2 = sum exp(v-m)*(v-m);  ent = log(s1) - s2/s1
    float s1 = 0.f, s2 = 0.f;
    for (int c = tid; c < ncols; c += NTHR) {
        float d = p[c] - rowmax;
        float e = expf(d);
        s1 += e;
        s2 += e * d;
    }
    sm[tid] = s1; __syncthreads();
    for (int s = NTHR / 2; s > 0; s >>= 1) { if (tid < s) sm[tid] += sm[tid + s]; __syncthreads(); }
    s1 = sm[0]; __syncthreads();
    sm[tid] = s2; __syncthreads();
    for (int s = NTHR / 2; s > 0; s >>= 1) { if (tid < s) sm[tid] += sm[tid + s]; __syncthreads(); }
    s2 = sm[0];

    if (tid == 0) {
        ent[row]  = logf(s1) - s2 / s1;
        yhat[row] = rowarg;
    }
}

// ------------------------ per-support inverse L2 norm ---------------------------
__global__ __launch_bounds__(NTHR) void compute_invnorms(
    const float* __restrict__ W, const float* __restrict__ z, float* __restrict__ invn)
{
    const int i = blockIdx.x;
    const float* row = (i < Cq) ? (W + (size_t)i * Dq) : (z + (size_t)(i - Cq) * Dq);
    float ss = 0.f;
    for (int d = threadIdx.x; d < Dq; d += NTHR) { float v = row[d]; ss += v * v; }
    __shared__ float red[NTHR];
    red[threadIdx.x] = ss; __syncthreads();
    for (int s = NTHR / 2; s > 0; s >>= 1) {
        if (threadIdx.x < s) red[threadIdx.x] += red[threadIdx.x + s];
        __syncthreads();
    }
    if (threadIdx.x == 0) invn[i] = 1.0f / fmaxf(sqrtf(red[0]), 1e-12f);
}

// --------- per-class gather + K smallest entropies (tie-break: smaller idx) -----
#define GATHER_CAP 5120    // >= Nsup; worst case all supports in one class
__global__ __launch_bounds__(NTHR) void select_topk(
    const float* __restrict__ ent, const int* __restrict__ yhat,
    const int* __restrict__ pK, int* __restrict__ selidx, int* __restrict__ selcnt)
{
    __shared__ float se[GATHER_CAP];
    __shared__ int   sidx[GATHER_CAP];
    __shared__ int   cnt;
    __shared__ float rbv[NTHR];
    __shared__ int   rbk[NTHR];
    __shared__ int   rbp[NTHR];

    const int c = blockIdx.x;
    int K = *pK; if (K > KMAX) K = KMAX;

    if (threadIdx.x == 0) cnt = 0;
    __syncthreads();
    for (int i = threadIdx.x; i < Nsup; i += NTHR) {
        if (yhat[i] == c) {
            int p = atomicAdd(&cnt, 1);
            se[p] = ent[i]; sidx[p] = i;
        }
    }
    __syncthreads();
    const int n = cnt;

    if (n <= K) {
        for (int i = threadIdx.x; i < n; i += NTHR) selidx[c * KMAX + i] = sidx[i];
        if (threadIdx.x == 0) selcnt[c] = n;
        return;
    }

    // iterative K-min selection (rare path with this data)
    for (int t = 0; t < K; t++) {
        float bv = FLT_MAX; int bk = 0x7fffffff; int bp = -1;
        for (int i = threadIdx.x; i < n; i += NTHR) {
            float v = se[i]; int key = sidx[i];
            if (v < bv || (v == bv && key < bk)) { bv = v; bk = key; bp = i; }
        }
        rbv[threadIdx.x] = bv; rbk[threadIdx.x] = bk; rbp[threadIdx.x] = bp;
        __syncthreads();
        for (int s = NTHR / 2; s > 0; s >>= 1) {
            if (threadIdx.x < s) {
                float v2 = rbv[threadIdx.x + s]; int k2 = rbk[threadIdx.x + s];
                if (v2 < rbv[threadIdx.x] ||
                    (v2 == rbv[threadIdx.x] && k2 < rbk[threadIdx.x])) {
                    rbv[threadIdx.x] = v2; rbk[threadIdx.x] = k2;
                    rbp[threadIdx.x] = rbp[threadIdx.x + s];
                }
            }
            __syncthreads();
        }
        if (threadIdx.x == 0) {
            int p = rbp[0];
            selidx[c * KMAX + t] = sidx[p];
            se[p] = FLT_MAX;
        }
        __syncthreads();
    }
    if (threadIdx.x == 0) selcnt[c] = K;
}

// ----- build normalized prototypes: wT[c,:] = normalize(sum_sel support/||.||) ---
__global__ __launch_bounds__(NTHR) void build_weights(
    const float* __restrict__ W, const float* __restrict__ z,
    const float* __restrict__ invn, const int* __restrict__ selidx,
    const int* __restrict__ selcnt, float* __restrict__ wT)
{
    const int c = blockIdx.x;
    const int n = selcnt[c];
    const int tid = threadIdx.x;
    float acc[Dq / NTHR];   // 8
#pragma unroll
    for (int j = 0; j < Dq / NTHR; j++) acc[j] = 0.f;

    for (int t = 0; t < n; t++) {
        int idx = selidx[c * KMAX + t];
        float s = invn[idx];
        const float* row = (idx < Cq) ? (W + (size_t)idx * Dq) : (z + (size_t)(idx - Cq) * Dq);
#pragma unroll
        for (int j = 0; j < Dq / NTHR; j++) acc[j] += s * row[tid + j * NTHR];
    }

    float ss = 0.f;
#pragma unroll
    for (int j = 0; j < Dq / NTHR; j++) ss += acc[j] * acc[j];
    __shared__ float red[NTHR];
    red[tid] = ss; __syncthreads();
    for (int s = NTHR / 2; s > 0; s >>= 1) {
        if (tid < s) red[tid] += red[tid + s];
        __syncthreads();
    }
    const float inv = 1.0f / fmaxf(sqrtf(red[0]), 1e-12f);
#pragma unroll
    for (int j = 0; j < Dq / NTHR; j++)
        wT[(size_t)c * Dq + tid + j * NTHR] = acc[j] * inv;
}

// --------------------------------- launch ---------------------------------------
extern "C" void kernel_launch(void* const* d_in, const int* in_sizes, int n_in,
                              void* d_out, int out_size)
{
    const float* z = (const float*)d_in[0];
    const float* W = (const float*)d_in[1];
    const int* pK  = (const int*)d_in[2];   // filter_K, read on device
    float* out = (float*)d_out;

    float *Pw, *Pz, *ent, *invn, *wT;
    int *yhat, *selidx, *selcnt;
    cudaGetSymbolAddress((void**)&Pw, g_Pw);
    cudaGetSymbolAddress((void**)&Pz, g_Pz);
    cudaGetSymbolAddress((void**)&ent, g_ent);
    cudaGetSymbolAddress((void**)&yhat, g_yhat);
    cudaGetSymbolAddress((void**)&invn, g_invn);
    cudaGetSymbolAddress((void**)&selidx, g_selidx);
    cudaGetSymbolAddress((void**)&selcnt, g_selcnt);
    cudaGetSymbolAddress((void**)&wT, g_wT);

    const int gnx = (Cq + BN - 1) / BN;           // 16

    // 1) P_w = W @ W^T ; entropy/argmax of warmup supports
    gemm_nt<<<dim3(gnx, (Cq + BM - 1) / BM), NTHR>>>(W, W, Pw, Cq, Cq, Dq);
    row_entropy_argmax<<<Cq, NTHR>>>(Pw, Cq, ent, yhat);

    // 2) P_z = z @ W^T ; entropy/argmax of test batch
    gemm_nt<<<dim3(gnx, (Bq + BM - 1) / BM), NTHR>>>(z, W, Pz, Bq, Cq, Dq);
    row_entropy_argmax<<<Bq, NTHR>>>(Pz, Cq, ent + Cq, yhat + Cq);

    // 3) support norms, per-class selection, prototype build
    compute_invnorms<<<Nsup, NTHR>>>(W, z, invn);
    select_topk<<<Cq, NTHR>>>(ent, yhat, pK, selidx, selcnt);
    build_weights<<<Cq, NTHR>>>(W, z, invn, selidx, selcnt, wT);

    // 4) out = z @ weights  (weights stored transposed -> same NT GEMM)
    gemm_nt<<<dim3(gnx, (Bq + BM - 1) / BM), NTHR>>>(z, wT, out, Bq, Cq, Dq);
}

// round 4
// speedup vs baseline: 2.5266x; 2.5266x over previous
#include <cuda_runtime.h>
#include <cuda_fp16.h>
#include <math.h>
#include <float.h>
#include <stdint.h>

// Problem-fixed shapes: z [B,D], W [C,D], out [B,C]
#define Bq 4096
#define Dq 2048
#define Cq 1000
#define Nsup (Bq + Cq)
#define KMAX 128
#define NTHR 256

// ---------------- scratch (static device globals; no allocation) ----------------
__device__ float g_Pw[Cq * Cq];
__device__ float g_Pz[Bq * Cq];
__device__ float g_ent[Nsup];
__device__ int   g_yhat[Nsup];
__device__ float g_invn[Nsup];
__device__ int   g_selidx[Cq * KMAX];
__device__ int   g_selcnt[Cq];

// fp16 2-limb splits (h + m carries 22 mantissa bits)
__device__ __half g_zh[Bq * Dq], g_zm[Bq * Dq];
__device__ __half g_Wh[Cq * Dq], g_Wm[Cq * Dq];
__device__ __half g_Th[Cq * Dq], g_Tm[Cq * Dq];

// ==================== mma.sync fp16 3-pair GEMM (C = A*B^T) =====================
// A limbs [M,2048], B limbs [N,2048] row-major fp16; C fp32 [M,N]
// C = Ah*Bh^T + Ah*Bm^T + Am*Bh^T  (fp32 accumulate)
#define BKC   64                      // K per chunk
#define NCH   (Dq / BKC)              // 32
#define TPAD  72                      // padded half-stride (conflict-free, 16B-aligned rows)
#define TILEB (128 * TPAD * 2)        // 18432 B
#define STAGEB (4 * TILEB)            // 73728 B (Ah, Am, Bh, Bm)
#define GSMEM (2 * STAGEB)            // 147456 B

__device__ __forceinline__ uint32_t smem_u32(const void* p) {
    uint32_t a;
    asm("{ .reg .u64 t; cvta.to.shared.u64 t, %1; cvt.u32.u64 %0, t; }" : "=r"(a) : "l"(p));
    return a;
}

__device__ __forceinline__ void cp16(uint32_t dst, const void* src, uint32_t srcsize) {
    asm volatile("cp.async.cg.shared.global [%0], [%1], 16, %2;"
                 :: "r"(dst), "l"(src), "r"(srcsize) : "memory");
}

__device__ __forceinline__ void mma16816(float* c, const uint32_t* a, const uint32_t* b) {
    asm volatile("mma.sync.aligned.m16n8k16.row.col.f32.f16.f16.f32 "
                 "{%0,%1,%2,%3}, {%4,%5,%6,%7}, {%8,%9}, {%0,%1,%2,%3};"
                 : "+f"(c[0]), "+f"(c[1]), "+f"(c[2]), "+f"(c[3])
                 : "r"(a[0]), "r"(a[1]), "r"(a[2]), "r"(a[3]), "r"(b[0]), "r"(b[1]));
}

__global__ __launch_bounds__(256) void gemm3p(
    const __half* __restrict__ Ah, const __half* __restrict__ Am,
    const __half* __restrict__ Bh, const __half* __restrict__ Bm,
    float* __restrict__ C, int M, int N)
{
    extern __shared__ char smem[];
    const uint32_t sbase = smem_u32(smem);
    const int tid = threadIdx.x;
    const int wid = tid >> 5;
    const int lane = tid & 31;
    const int mBase = blockIdx.y * 128;
    const int nBase = blockIdx.x * 128;
    const int wm = (wid & 1) * 64;        // warp row offset in tile
    const int wn = (wid >> 1) * 32;       // warp col offset in tile

    const __half* srcs[4] = { Ah, Am, Bh, Bm };

    float acc[4][4][4];
#pragma unroll
    for (int i = 0; i < 4; i++)
#pragma unroll
        for (int j = 0; j < 4; j++)
#pragma unroll
            for (int q = 0; q < 4; q++) acc[i][j][q] = 0.f;

    // ---- chunk loader: 4 tiles x 128 rows x 128 B, 16 cp.async per thread ----
    auto load_chunk = [&](int c, int stage) {
        const uint32_t stBase = sbase + stage * STAGEB;
#pragma unroll
        for (int i = 0; i < 16; i++) {
            const int idx = tid + i * 256;          // 0..4095
            const int t = idx >> 10;                // tile 0..3
            const int r = (idx >> 3) & 127;         // row 0..127
            const int s = idx & 7;                  // 16B segment 0..7
            const int rb = ((t < 2) ? mBase : nBase) + r;
            const int bound = (t < 2) ? M : N;
            const uint32_t dst = stBase + t * TILEB + r * (TPAD * 2) + s * 16;
            const __half* src = srcs[t] + (size_t)rb * Dq + c * BKC + s * 8;
            cp16(dst, src, (rb < bound) ? 16u : 0u);
        }
        asm volatile("cp.async.commit_group;" ::: "memory");
    };

    load_chunk(0, 0);

    for (int c = 0; c < NCH; c++) {
        if (c + 1 < NCH) {
            load_chunk(c + 1, (c + 1) & 1);
            asm volatile("cp.async.wait_group 1;" ::: "memory");
        } else {
            asm volatile("cp.async.wait_group 0;" ::: "memory");
        }
        __syncthreads();

        const char* st = smem + (c & 1) * STAGEB;
        const __half* As_h = (const __half*)(st);
        const __half* As_m = (const __half*)(st + TILEB);
        const __half* Bs_h = (const __half*)(st + 2 * TILEB);
        const __half* Bs_m = (const __half*)(st + 3 * TILEB);

#pragma unroll
        for (int k16 = 0; k16 < BKC / 16; k16++) {
            const int kb = k16 * 16 + (lane & 3) * 2;
            uint32_t ah[4][4], am[4][4], bh[4][2], bm[4][2];
#pragma unroll
            for (int mt = 0; mt < 4; mt++) {
                const int row = wm + mt * 16 + (lane >> 2);
                ah[mt][0] = *(const uint32_t*)&As_h[row * TPAD + kb];
                ah[mt][1] = *(const uint32_t*)&As_h[(row + 8) * TPAD + kb];
                ah[mt][2] = *(const uint32_t*)&As_h[row * TPAD + kb + 8];
                ah[mt][3] = *(const uint32_t*)&As_h[(row + 8) * TPAD + kb + 8];
                am[mt][0] = *(const uint32_t*)&As_m[row * TPAD + kb];
                am[mt][1] = *(const uint32_t*)&As_m[(row + 8) * TPAD + kb];
                am[mt][2] = *(const uint32_t*)&As_m[row * TPAD + kb + 8];
                am[mt][3] = *(const uint32_t*)&As_m[(row + 8) * TPAD + kb + 8];
            }
#pragma unroll
            for (int nt = 0; nt < 4; nt++) {
                const int n = wn + nt * 8 + (lane >> 2);
                bh[nt][0] = *(const uint32_t*)&Bs_h[n * TPAD + kb];
                bh[nt][1] = *(const uint32_t*)&Bs_h[n * TPAD + kb + 8];
                bm[nt][0] = *(const uint32_t*)&Bs_m[n * TPAD + kb];
                bm[nt][1] = *(const uint32_t*)&Bs_m[n * TPAD + kb + 8];
            }
#pragma unroll
            for (int mt = 0; mt < 4; mt++)
#pragma unroll
                for (int nt = 0; nt < 4; nt++) {
                    mma16816(acc[mt][nt], ah[mt], bh[nt]);
                    mma16816(acc[mt][nt], ah[mt], bm[nt]);
                    mma16816(acc[mt][nt], am[mt], bh[nt]);
                }
        }
        __syncthreads();
    }

    // ---- epilogue ----
#pragma unroll
    for (int mt = 0; mt < 4; mt++) {
        const int row0 = mBase + wm + mt * 16 + (lane >> 2);
#pragma unroll
        for (int nt = 0; nt < 4; nt++) {
            const int col0 = nBase + wn + nt * 8 + (lane & 3) * 2;
            if (col0 < N) {
                if (row0 < M)
                    *(float2*)&C[(size_t)row0 * N + col0] =
                        make_float2(acc[mt][nt][0], acc[mt][nt][1]);
                if (row0 + 8 < M)
                    *(float2*)&C[(size_t)(row0 + 8) * N + col0] =
                        make_float2(acc[mt][nt][2], acc[mt][nt][3]);
            }
        }
    }
}

// ---------------- split fp32 -> 2 fp16 limbs ----------------
__global__ __launch_bounds__(NTHR) void split2(
    const float* __restrict__ X, __half* __restrict__ h, __half* __restrict__ m, int n)
{
    int i = blockIdx.x * blockDim.x + threadIdx.x;
    if (i < n) {
        float x = X[i];
        __half hb = __float2half_rn(x);
        float r1 = x - __half2float(hb);
        h[i] = hb; m[i] = __float2half_rn(r1);
    }
}

// ------------- per-row entropy + argmax (first max) -------
__global__ __launch_bounds__(NTHR) void row_entropy_argmax(
    const float* __restrict__ P, int ncols,
    float* __restrict__ ent, int* __restrict__ yhat)
{
    const int row = blockIdx.x;
    const float* p = P + (size_t)row * ncols;
    const int tid = threadIdx.x;
    __shared__ float sm[NTHR];
    __shared__ int   si[NTHR];

    float m = -FLT_MAX; int mi = 0x7fffffff;
    for (int c = tid; c < ncols; c += NTHR) {
        float v = p[c];
        if (v > m) { m = v; mi = c; }
    }
    sm[tid] = m; si[tid] = mi;
    __syncthreads();
    for (int s = NTHR / 2; s > 0; s >>= 1) {
        if (tid < s) {
            float m2 = sm[tid + s]; int i2 = si[tid + s];
            if (m2 > sm[tid] || (m2 == sm[tid] && i2 < si[tid])) { sm[tid] = m2; si[tid] = i2; }
        }
        __syncthreads();
    }
    const float rowmax = sm[0];
    const int rowarg = si[0];
    __syncthreads();

    float s1 = 0.f, s2 = 0.f;
    for (int c = tid; c < ncols; c += NTHR) {
        float d = p[c] - rowmax;
        float e = expf(d);
        s1 += e; s2 += e * d;
    }
    sm[tid] = s1; __syncthreads();
    for (int s = NTHR / 2; s > 0; s >>= 1) { if (tid < s) sm[tid] += sm[tid + s]; __syncthreads(); }
    s1 = sm[0]; __syncthreads();
    sm[tid] = s2; __syncthreads();
    for (int s = NTHR / 2; s > 0; s >>= 1) { if (tid < s) sm[tid] += sm[tid + s]; __syncthreads(); }
    s2 = sm[0];

    if (tid == 0) { ent[row] = logf(s1) - s2 / s1; yhat[row] = rowarg; }
}

// ------------------------ per-support inverse L2 norm ---------------------------
__global__ __launch_bounds__(NTHR) void compute_invnorms(
    const float* __restrict__ W, const float* __restrict__ z, float* __restrict__ invn)
{
    const int i = blockIdx.x;
    const float* row = (i < Cq) ? (W + (size_t)i * Dq) : (z + (size_t)(i - Cq) * Dq);
    float ss = 0.f;
    for (int d = threadIdx.x; d < Dq; d += NTHR) { float v = row[d]; ss += v * v; }
    __shared__ float red[NTHR];
    red[threadIdx.x] = ss; __syncthreads();
    for (int s = NTHR / 2; s > 0; s >>= 1) {
        if (threadIdx.x < s) red[threadIdx.x] += red[threadIdx.x + s];
        __syncthreads();
    }
    if (threadIdx.x == 0) invn[i] = 1.0f / fmaxf(sqrtf(red[0]), 1e-12f);
}

// --------- per-class gather + K smallest entropies (tie-break: smaller idx) -----
#define GATHER_CAP 5120
__global__ __launch_bounds__(NTHR) void select_topk(
    const float* __restrict__ ent, const int* __restrict__ yhat,
    const int* __restrict__ pK, int* __restrict__ selidx, int* __restrict__ selcnt)
{
    __shared__ float se[GATHER_CAP];
    __shared__ int   sidx[GATHER_CAP];
    __shared__ int   cnt;
    __shared__ float rbv[NTHR];
    __shared__ int   rbk[NTHR];
    __shared__ int   rbp[NTHR];

    const int c = blockIdx.x;
    int K = *pK; if (K > KMAX) K = KMAX;

    if (threadIdx.x == 0) cnt = 0;
    __syncthreads();
    for (int i = threadIdx.x; i < Nsup; i += NTHR) {
        if (yhat[i] == c) {
            int p = atomicAdd(&cnt, 1);
            se[p] = ent[i]; sidx[p] = i;
        }
    }
    __syncthreads();
    const int n = cnt;

    if (n <= K) {
        for (int i = threadIdx.x; i < n; i += NTHR) selidx[c * KMAX + i] = sidx[i];
        if (threadIdx.x == 0) selcnt[c] = n;
        return;
    }
    for (int t = 0; t < K; t++) {
        float bv = FLT_MAX; int bk = 0x7fffffff; int bp = -1;
        for (int i = threadIdx.x; i < n; i += NTHR) {
            float v = se[i]; int key = sidx[i];
            if (v < bv || (v == bv && key < bk)) { bv = v; bk = key; bp = i; }
        }
        rbv[threadIdx.x] = bv; rbk[threadIdx.x] = bk; rbp[threadIdx.x] = bp;
        __syncthreads();
        for (int s = NTHR / 2; s > 0; s >>= 1) {
            if (threadIdx.x < s) {
                float v2 = rbv[threadIdx.x + s]; int k2 = rbk[threadIdx.x + s];
                if (v2 < rbv[threadIdx.x] ||
                    (v2 == rbv[threadIdx.x] && k2 < rbk[threadIdx.x])) {
                    rbv[threadIdx.x] = v2; rbk[threadIdx.x] = k2;
                    rbp[threadIdx.x] = rbp[threadIdx.x + s];
                }
            }
            __syncthreads();
        }
        if (threadIdx.x == 0) {
            int p = rbp[0];
            selidx[c * KMAX + t] = sidx[p];
            se[p] = FLT_MAX;
        }
        __syncthreads();
    }
    if (threadIdx.x == 0) selcnt[c] = K;
}

// ----- build normalized prototypes, emit fp16 limb splits of weights^T ----------
__global__ __launch_bounds__(NTHR) void build_weights(
    const float* __restrict__ W, const float* __restrict__ z,
    const float* __restrict__ invn, const int* __restrict__ selidx,
    const int* __restrict__ selcnt,
    __half* __restrict__ Th, __half* __restrict__ Tm)
{
    const int c = blockIdx.x;
    const int n = selcnt[c];
    const int tid = threadIdx.x;
    float acc[Dq / NTHR];
#pragma unroll
    for (int j = 0; j < Dq / NTHR; j++) acc[j] = 0.f;

    for (int t = 0; t < n; t++) {
        int idx = selidx[c * KMAX + t];
        float s = invn[idx];
        const float* row = (idx < Cq) ? (W + (size_t)idx * Dq) : (z + (size_t)(idx - Cq) * Dq);
#pragma unroll
        for (int j = 0; j < Dq / NTHR; j++) acc[j] += s * row[tid + j * NTHR];
    }

    float ss = 0.f;
#pragma unroll
    for (int j = 0; j < Dq / NTHR; j++) ss += acc[j] * acc[j];
    __shared__ float red[NTHR];
    red[tid] = ss; __syncthreads();
    for (int s = NTHR / 2; s > 0; s >>= 1) {
        if (tid < s) red[tid] += red[tid + s];
        __syncthreads();
    }
    const float inv = 1.0f / fmaxf(sqrtf(red[0]), 1e-12f);
#pragma unroll
    for (int j = 0; j < Dq / NTHR; j++) {
        float x = acc[j] * inv;
        size_t o = (size_t)c * Dq + tid + j * NTHR;
        __half hb = __float2half_rn(x);
        float r1 = x - __half2float(hb);
        Th[o] = hb; Tm[o] = __float2half_rn(r1);
    }
}

// --------------------------------- launch ---------------------------------------
extern "C" void kernel_launch(void* const* d_in, const int* in_sizes, int n_in,
                              void* d_out, int out_size)
{
    const float* z = (const float*)d_in[0];
    const float* W = (const float*)d_in[1];
    const int* pK  = (const int*)d_in[2];
    float* out = (float*)d_out;

    float *Pw, *Pz, *ent, *invn;
    int *yhat, *selidx, *selcnt;
    __half *zh, *zm, *Wh, *Wm, *Th, *Tm;
    cudaGetSymbolAddress((void**)&Pw, g_Pw);
    cudaGetSymbolAddress((void**)&Pz, g_Pz);
    cudaGetSymbolAddress((void**)&ent, g_ent);
    cudaGetSymbolAddress((void**)&yhat, g_yhat);
    cudaGetSymbolAddress((void**)&invn, g_invn);
    cudaGetSymbolAddress((void**)&selidx, g_selidx);
    cudaGetSymbolAddress((void**)&selcnt, g_selcnt);
    cudaGetSymbolAddress((void**)&zh, g_zh); cudaGetSymbolAddress((void**)&zm, g_zm);
    cudaGetSymbolAddress((void**)&Wh, g_Wh); cudaGetSymbolAddress((void**)&Wm, g_Wm);
    cudaGetSymbolAddress((void**)&Th, g_Th); cudaGetSymbolAddress((void**)&Tm, g_Tm);

    cudaFuncSetAttribute(gemm3p, cudaFuncAttributeMaxDynamicSharedMemorySize, GSMEM);

    // limb splits
    split2<<<(Bq * Dq + NTHR - 1) / NTHR, NTHR>>>(z, zh, zm, Bq * Dq);
    split2<<<(Cq * Dq + NTHR - 1) / NTHR, NTHR>>>(W, Wh, Wm, Cq * Dq);

    // 1) P_w = W @ W^T, entropy/argmax
    gemm3p<<<dim3(8, 8), 256, GSMEM>>>(Wh, Wm, Wh, Wm, Pw, Cq, Cq);
    row_entropy_argmax<<<Cq, NTHR>>>(Pw, Cq, ent, yhat);

    // 2) P_z = z @ W^T, entropy/argmax
    gemm3p<<<dim3(8, 32), 256, GSMEM>>>(zh, zm, Wh, Wm, Pz, Bq, Cq);
    row_entropy_argmax<<<Bq, NTHR>>>(Pz, Cq, ent + Cq, yhat + Cq);

    // 3) norms, per-class selection, prototype build (+ fp16 limb split of weights)
    compute_invnorms<<<Nsup, NTHR>>>(W, z, invn);
    select_topk<<<Cq, NTHR>>>(ent, yhat, pK, selidx, selcnt);
    build_weights<<<Cq, NTHR>>>(W, z, invn, selidx, selcnt, Th, Tm);

    // 4) out = z @ weights
    gemm3p<<<dim3(8, 32), 256, GSMEM>>>(zh, zm, Th, Tm, out, Bq, Cq);
}

// round 5
// speedup vs baseline: 2.9595x; 1.1713x over previous
#include <cuda_runtime.h>
#include <cuda_fp16.h>
#include <math.h>
#include <float.h>
#include <stdint.h>

// Problem-fixed shapes: z [B,D], W [C,D], out [B,C]
#define Bq 4096
#define Dq 2048
#define Cq 1000
#define Nsup (Bq + Cq)   // 5096, supports ordered [W; z]
#define KMAX 128
#define NTHR 256

// ---------------- scratch (static device globals; no allocation) ----------------
__device__ float g_P[Nsup * Cq];          // 20.4 MB merged logits
__device__ float g_ent[Nsup];
__device__ int   g_yhat[Nsup];
__device__ float g_invn[Nsup];
__device__ int   g_selidx[Cq * KMAX];
__device__ int   g_selcnt[Cq];
__device__ __half g_Ah[Nsup * Dq], g_Am[Nsup * Dq];   // fp16 limb splits of [W; z]
__device__ __half g_Th[Cq * Dq];                      // fp16 high limb of weights^T

// ==================== mma.sync fp16 multi-pair GEMM (C = A*B^T) =================
// MODE 3: C = Ah*Bh^T + Ah*Bm^T + Am*Bh^T   (logits, ~fp32 accuracy)
// MODE 2: C = Ah*Bh^T + Am*Bh^T             (final, B single-limb)
#define BKC   32                       // K per chunk
#define NCH   (Dq / BKC)               // 64
#define TPADH 40                       // padded half-stride: 80 B rows, conflict-free
#define TILEB (128 * TPADH * 2)        // 10240 B
#define STAGE4 (4 * TILEB)             // 40960 B (Ah, Am, Bh, Bm)
#define GSMEM (2 * STAGE4)             // 81920 B -> 2 CTAs/SM

__device__ __forceinline__ uint32_t smem_u32(const void* p) {
    uint32_t a;
    asm("{ .reg .u64 t; cvta.to.shared.u64 t, %1; cvt.u32.u64 %0, t; }" : "=r"(a) : "l"(p));
    return a;
}
__device__ __forceinline__ void cp16(uint32_t dst, const void* src, uint32_t srcsize) {
    asm volatile("cp.async.cg.shared.global [%0], [%1], 16, %2;"
                 :: "r"(dst), "l"(src), "r"(srcsize) : "memory");
}
__device__ __forceinline__ void mma16816(float* c, const uint32_t* a, const uint32_t* b) {
    asm volatile("mma.sync.aligned.m16n8k16.row.col.f32.f16.f16.f32 "
                 "{%0,%1,%2,%3}, {%4,%5,%6,%7}, {%8,%9}, {%0,%1,%2,%3};"
                 : "+f"(c[0]), "+f"(c[1]), "+f"(c[2]), "+f"(c[3])
                 : "r"(a[0]), "r"(a[1]), "r"(a[2]), "r"(a[3]), "r"(b[0]), "r"(b[1]));
}

template<int MODE>
__global__ __launch_bounds__(256, 2) void gemm_k(
    const __half* __restrict__ Ah, const __half* __restrict__ Am,
    const __half* __restrict__ Bh, const __half* __restrict__ Bm,
    float* __restrict__ C, int M, int N)
{
    extern __shared__ char smem[];
    const uint32_t sbase = smem_u32(smem);
    const int tid = threadIdx.x;
    const int wid = tid >> 5;
    const int lane = tid & 31;
    const int mBase = blockIdx.y * 128;
    const int nBase = blockIdx.x * 128;
    const int wm = (wid & 1) * 64;
    const int wn = (wid >> 1) * 32;

    const __half* srcs[4] = { Ah, Am, Bh, Bm };

    float acc[4][4][4];
#pragma unroll
    for (int i = 0; i < 4; i++)
#pragma unroll
        for (int j = 0; j < 4; j++)
#pragma unroll
            for (int q = 0; q < 4; q++) acc[i][j][q] = 0.f;

    // chunk loader: tiles {Ah,Am,Bh[,Bm]} x 128 rows x 64 B
    auto load_chunk = [&](int c, int stage) {
        const uint32_t stBase = sbase + stage * STAGE4;
#pragma unroll
        for (int i = 0; i < 8; i++) {
            if (MODE == 2 && i >= 6) continue;      // skip Bm tile
            const int idx = tid + i * 256;          // 0..2047
            const int t = i >> 1;                   // tile 0..3 (uniform per i)
            const int r = (idx >> 2) & 127;         // row 0..127
            const int s = idx & 3;                  // 16B segment 0..3
            const int rb = ((t < 2) ? mBase : nBase) + r;
            const int bound = (t < 2) ? M : N;
            const uint32_t dst = stBase + t * TILEB + r * (TPADH * 2) + s * 16;
            const __half* src = srcs[t] + (size_t)rb * Dq + c * BKC + s * 8;
            cp16(dst, src, (rb < bound) ? 16u : 0u);
        }
        asm volatile("cp.async.commit_group;" ::: "memory");
    };

    load_chunk(0, 0);

    for (int c = 0; c < NCH; c++) {
        if (c + 1 < NCH) {
            load_chunk(c + 1, (c + 1) & 1);
            asm volatile("cp.async.wait_group 1;" ::: "memory");
        } else {
            asm volatile("cp.async.wait_group 0;" ::: "memory");
        }
        __syncthreads();

        const char* st = smem + (c & 1) * STAGE4;
        const __half* As_h = (const __half*)(st);
        const __half* As_m = (const __half*)(st + TILEB);
        const __half* Bs_h = (const __half*)(st + 2 * TILEB);
        const __half* Bs_m = (const __half*)(st + 3 * TILEB);

#pragma unroll
        for (int k16 = 0; k16 < BKC / 16; k16++) {
            const int kb = k16 * 16 + (lane & 3) * 2;
            uint32_t bh[4][2], bm[4][2];
#pragma unroll
            for (int nt = 0; nt < 4; nt++) {
                const int n = wn + nt * 8 + (lane >> 2);
                bh[nt][0] = *(const uint32_t*)&Bs_h[n * TPADH + kb];
                bh[nt][1] = *(const uint32_t*)&Bs_h[n * TPADH + kb + 8];
                if (MODE == 3) {
                    bm[nt][0] = *(const uint32_t*)&Bs_m[n * TPADH + kb];
                    bm[nt][1] = *(const uint32_t*)&Bs_m[n * TPADH + kb + 8];
                }
            }
#pragma unroll
            for (int mt = 0; mt < 4; mt++) {
                const int row = wm + mt * 16 + (lane >> 2);
                uint32_t ah[4], am[4];
                ah[0] = *(const uint32_t*)&As_h[row * TPADH + kb];
                ah[1] = *(const uint32_t*)&As_h[(row + 8) * TPADH + kb];
                ah[2] = *(const uint32_t*)&As_h[row * TPADH + kb + 8];
                ah[3] = *(const uint32_t*)&As_h[(row + 8) * TPADH + kb + 8];
                am[0] = *(const uint32_t*)&As_m[row * TPADH + kb];
                am[1] = *(const uint32_t*)&As_m[(row + 8) * TPADH + kb];
                am[2] = *(const uint32_t*)&As_m[row * TPADH + kb + 8];
                am[3] = *(const uint32_t*)&As_m[(row + 8) * TPADH + kb + 8];
#pragma unroll
                for (int nt = 0; nt < 4; nt++) {
                    mma16816(acc[mt][nt], ah, bh[nt]);
                    if (MODE == 3) mma16816(acc[mt][nt], ah, bm[nt]);
                    mma16816(acc[mt][nt], am, bh[nt]);
                }
            }
        }
        __syncthreads();
    }

    // epilogue (same pattern as validated R4 kernel)
#pragma unroll
    for (int mt = 0; mt < 4; mt++) {
        const int row0 = mBase + wm + mt * 16 + (lane >> 2);
#pragma unroll
        for (int nt = 0; nt < 4; nt++) {
            const int col0 = nBase + wn + nt * 8 + (lane & 3) * 2;
            if (col0 < N) {
                if (row0 < M)
                    *(float2*)&C[(size_t)row0 * N + col0] =
                        make_float2(acc[mt][nt][0], acc[mt][nt][1]);
                if (row0 + 8 < M)
                    *(float2*)&C[(size_t)(row0 + 8) * N + col0] =
                        make_float2(acc[mt][nt][2], acc[mt][nt][3]);
            }
        }
    }
}

// -------- fused: split fp32 -> 2 fp16 limbs + inverse L2 norm, one row/block ----
__global__ __launch_bounds__(NTHR) void split_norm(
    const float* __restrict__ z, const float* __restrict__ W,
    __half* __restrict__ Ah, __half* __restrict__ Am, float* __restrict__ invn)
{
    const int r = blockIdx.x;   // support index: [0,Cq) = W, [Cq,Nsup) = z
    const float* src = (r < Cq) ? (W + (size_t)r * Dq) : (z + (size_t)(r - Cq) * Dq);
    const int tid = threadIdx.x;
    float ss = 0.f;
#pragma unroll
    for (int j = 0; j < Dq / NTHR; j++) {
        const int i = tid + j * NTHR;
        float x = src[i];
        __half hb = __float2half_rn(x);
        float rem = x - __half2float(hb);
        Ah[(size_t)r * Dq + i] = hb;
        Am[(size_t)r * Dq + i] = __float2half_rn(rem);
        ss += x * x;
    }
    __shared__ float red[NTHR];
    red[tid] = ss; __syncthreads();
    for (int s = NTHR / 2; s > 0; s >>= 1) {
        if (tid < s) red[tid] += red[tid + s];
        __syncthreads();
    }
    if (tid == 0) invn[r] = 1.0f / fmaxf(sqrtf(red[0]), 1e-12f);
}

// ------------- per-row entropy + argmax (first max on ties) -------
__global__ __launch_bounds__(NTHR) void row_entropy_argmax(
    const float* __restrict__ P, int ncols,
    float* __restrict__ ent, int* __restrict__ yhat)
{
    const int row = blockIdx.x;
    const float* p = P + (size_t)row * ncols;
    const int tid = threadIdx.x;
    __shared__ float sm[NTHR];
    __shared__ int   si[NTHR];

    float m = -FLT_MAX; int mi = 0x7fffffff;
    for (int c = tid; c < ncols; c += NTHR) {
        float v = p[c];
        if (v > m) { m = v; mi = c; }
    }
    sm[tid] = m; si[tid] = mi;
    __syncthreads();
    for (int s = NTHR / 2; s > 0; s >>= 1) {
        if (tid < s) {
            float m2 = sm[tid + s]; int i2 = si[tid + s];
            if (m2 > sm[tid] || (m2 == sm[tid] && i2 < si[tid])) { sm[tid] = m2; si[tid] = i2; }
        }
        __syncthreads();
    }
    const float rowmax = sm[0];
    const int rowarg = si[0];
    __syncthreads();

    float s1 = 0.f, s2 = 0.f;
    for (int c = tid; c < ncols; c += NTHR) {
        float d = p[c] - rowmax;
        float e = expf(d);
        s1 += e; s2 += e * d;
    }
    sm[tid] = s1; __syncthreads();
    for (int s = NTHR / 2; s > 0; s >>= 1) { if (tid < s) sm[tid] += sm[tid + s]; __syncthreads(); }
    s1 = sm[0]; __syncthreads();
    sm[tid] = s2; __syncthreads();
    for (int s = NTHR / 2; s > 0; s >>= 1) { if (tid < s) sm[tid] += sm[tid + s]; __syncthreads(); }
    s2 = sm[0];

    if (tid == 0) { ent[row] = logf(s1) - s2 / s1; yhat[row] = rowarg; }
}

// --------- per-class gather + K smallest entropies (tie-break: smaller idx) -----
#define GATHER_CAP 5120
__global__ __launch_bounds__(NTHR) void select_topk(
    const float* __restrict__ ent, const int* __restrict__ yhat,
    const int* __restrict__ pK, int* __restrict__ selidx, int* __restrict__ selcnt)
{
    __shared__ float se[GATHER_CAP];
    __shared__ int   sidx[GATHER_CAP];
    __shared__ int   cnt;
    __shared__ float rbv[NTHR];
    __shared__ int   rbk[NTHR];
    __shared__ int   rbp[NTHR];

    const int c = blockIdx.x;
    int K = *pK; if (K > KMAX) K = KMAX;

    if (threadIdx.x == 0) cnt = 0;
    __syncthreads();
    for (int i = threadIdx.x; i < Nsup; i += NTHR) {
        if (yhat[i] == c) {
            int p = atomicAdd(&cnt, 1);
            se[p] = ent[i]; sidx[p] = i;
        }
    }
    __syncthreads();
    const int n = cnt;

    if (n <= K) {
        for (int i = threadIdx.x; i < n; i += NTHR) selidx[c * KMAX + i] = sidx[i];
        if (threadIdx.x == 0) selcnt[c] = n;
        return;
    }
    for (int t = 0; t < K; t++) {
        float bv = FLT_MAX; int bk = 0x7fffffff; int bp = -1;
        for (int i = threadIdx.x; i < n; i += NTHR) {
            float v = se[i]; int key = sidx[i];
            if (v < bv || (v == bv && key < bk)) { bv = v; bk = key; bp = i; }
        }
        rbv[threadIdx.x] = bv; rbk[threadIdx.x] = bk; rbp[threadIdx.x] = bp;
        __syncthreads();
        for (int s = NTHR / 2; s > 0; s >>= 1) {
            if (threadIdx.x < s) {
                float v2 = rbv[threadIdx.x + s]; int k2 = rbk[threadIdx.x + s];
                if (v2 < rbv[threadIdx.x] ||
                    (v2 == rbv[threadIdx.x] && k2 < rbk[threadIdx.x])) {
                    rbv[threadIdx.x] = v2; rbk[threadIdx.x] = k2;
                    rbp[threadIdx.x] = rbp[threadIdx.x + s];
                }
            }
            __syncthreads();
        }
        if (threadIdx.x == 0) {
            int p = rbp[0];
            selidx[c * KMAX + t] = sidx[p];
            se[p] = FLT_MAX;
        }
        __syncthreads();
    }
    if (threadIdx.x == 0) selcnt[c] = K;
}

// ----- build normalized prototypes, emit fp16 high limb of weights^T ------------
__global__ __launch_bounds__(NTHR) void build_weights(
    const float* __restrict__ W, const float* __restrict__ z,
    const float* __restrict__ invn, const int* __restrict__ selidx,
    const int* __restrict__ selcnt, __half* __restrict__ Th)
{
    const int c = blockIdx.x;
    const int n = selcnt[c];
    const int tid = threadIdx.x;
    float acc[Dq / NTHR];
#pragma unroll
    for (int j = 0; j < Dq / NTHR; j++) acc[j] = 0.f;

    for (int t = 0; t < n; t++) {
        int idx = selidx[c * KMAX + t];
        float s = invn[idx];
        const float* row = (idx < Cq) ? (W + (size_t)idx * Dq) : (z + (size_t)(idx - Cq) * Dq);
#pragma unroll
        for (int j = 0; j < Dq / NTHR; j++) acc[j] += s * row[tid + j * NTHR];
    }

    float ss = 0.f;
#pragma unroll
    for (int j = 0; j < Dq / NTHR; j++) ss += acc[j] * acc[j];
    __shared__ float red[NTHR];
    red[tid] = ss; __syncthreads();
    for (int s = NTHR / 2; s > 0; s >>= 1) {
        if (tid < s) red[tid] += red[tid + s];
        __syncthreads();
    }
    const float inv = 1.0f / fmaxf(sqrtf(red[0]), 1e-12f);
#pragma unroll
    for (int j = 0; j < Dq / NTHR; j++)
        Th[(size_t)c * Dq + tid + j * NTHR] = __float2half_rn(acc[j] * inv);
}

// --------------------------------- launch ---------------------------------------
extern "C" void kernel_launch(void* const* d_in, const int* in_sizes, int n_in,
                              void* d_out, int out_size)
{
    const float* z = (const float*)d_in[0];
    const float* W = (const float*)d_in[1];
    const int* pK  = (const int*)d_in[2];
    float* out = (float*)d_out;

    float *P, *ent, *invn;
    int *yhat, *selidx, *selcnt;
    __half *Ah, *Am, *Th;
    cudaGetSymbolAddress((void**)&P, g_P);
    cudaGetSymbolAddress((void**)&ent, g_ent);
    cudaGetSymbolAddress((void**)&yhat, g_yhat);
    cudaGetSymbolAddress((void**)&invn, g_invn);
    cudaGetSymbolAddress((void**)&selidx, g_selidx);
    cudaGetSymbolAddress((void**)&selcnt, g_selcnt);
    cudaGetSymbolAddress((void**)&Ah, g_Ah);
    cudaGetSymbolAddress((void**)&Am, g_Am);
    cudaGetSymbolAddress((void**)&Th, g_Th);

    cudaFuncSetAttribute(gemm_k<3>, cudaFuncAttributeMaxDynamicSharedMemorySize, GSMEM);
    cudaFuncSetAttribute(gemm_k<2>, cudaFuncAttributeMaxDynamicSharedMemorySize, GSMEM);

    // 0) limb split of [W; z] + per-support inverse norms
    split_norm<<<Nsup, NTHR>>>(z, W, Ah, Am, invn);

    // 1) merged logits: P[5096,1000] = [W;z] @ W^T  (3-pair, ~fp32 accuracy)
    gemm_k<3><<<dim3(8, 40), 256, GSMEM>>>(Ah, Am, Ah, Am, P, Nsup, Cq);

    // 2) entropy + argmax over all supports
    row_entropy_argmax<<<Nsup, NTHR>>>(P, Cq, ent, yhat);

    // 3) per-class selection
    select_topk<<<Cq, NTHR>>>(ent, yhat, pK, selidx, selcnt);

    // 4) prototypes (fp16 high limb only — final GEMM is 2-pair)
    build_weights<<<Cq, NTHR>>>(W, z, invn, selidx, selcnt, Th);

    // 5) out = z @ weights   (A = z limbs at offset Cq rows; B = Th single-limb)
    gemm_k<2><<<dim3(8, 32), 256, GSMEM>>>(Ah + (size_t)Cq * Dq, Am + (size_t)Cq * Dq,
                                           Th, Th, out, Bq, Cq);
}

// round 9
// speedup vs baseline: 3.4812x; 1.1763x over previous
#include <cuda_runtime.h>
#include <cuda_fp16.h>
#include <math.h>
#include <float.h>
#include <stdint.h>

// Problem-fixed shapes: z [B,D], W [C,D], out [B,C]
#define Bq 4096
#define Dq 2048
#define Cq 1000
#define Nsup (Bq + Cq)   // 5096, supports ordered [W; z]
#define KMAX 128
#define NTHR 256
#define BCAP 5096        // per-class bucket capacity (worst case)

// ---------------- scratch (static device globals; no allocation) ----------------
__device__ float g_P[Nsup * Cq];          // 20.4 MB merged logits (split-K accum)
__device__ float g_ent[Nsup];
__device__ float g_invn[Nsup];
__device__ int   g_cnt[Cq];
__device__ float g_bktE[Cq * BCAP];       // per-class entropy buckets
__device__ int   g_bktI[Cq * BCAP];
__device__ int   g_selidx[Cq * KMAX];
__device__ int   g_selcnt[Cq];
__device__ __half g_Ah[Nsup * Dq], g_Am[Nsup * Dq];   // fp16 limb splits of [W; z]
__device__ __half g_Th[Cq * Dq];                      // fp16 high limb of weights^T

// ==================== mma.sync fp16 multi-pair GEMM (C = A*B^T) =================
// MODE 3: C = Ah*Bh^T + Ah*Bm^T + Am*Bh^T   (logits, ~fp32 accuracy)
// MODE 1: C = Ah*Bh^T                        (final, both operands single-limb)
#define BKC   32                       // K per chunk
#define NCH   (Dq / BKC)               // 64
#define TPADH 40                       // padded half-stride: 80 B rows, conflict-free
#define TILEB (128 * TPADH * 2)        // 10240 B
#define STAGE4 (4 * TILEB)             // 40960 B (Ah, Am, Bh, Bm)
#define GSMEM (2 * STAGE4)             // 81920 B -> 2 CTAs/SM

__device__ __forceinline__ uint32_t smem_u32(const void* p) {
    uint32_t a;
    asm("{ .reg .u64 t; cvta.to.shared.u64 t, %1; cvt.u32.u64 %0, t; }" : "=r"(a) : "l"(p));
    return a;
}
__device__ __forceinline__ void cp16(uint32_t dst, const void* src, uint32_t srcsize) {
    asm volatile("cp.async.cg.shared.global [%0], [%1], 16, %2;"
                 :: "r"(dst), "l"(src), "r"(srcsize) : "memory");
}
__device__ __forceinline__ void mma16816(float* c, const uint32_t* a, const uint32_t* b) {
    asm volatile("mma.sync.aligned.m16n8k16.row.col.f32.f16.f16.f32 "
                 "{%0,%1,%2,%3}, {%4,%5,%6,%7}, {%8,%9}, {%0,%1,%2,%3};"
                 : "+f"(c[0]), "+f"(c[1]), "+f"(c[2]), "+f"(c[3])
                 : "r"(a[0]), "r"(a[1]), "r"(a[2]), "r"(a[3]), "r"(b[0]), "r"(b[1]));
}

template<int MODE, bool SPLITK>
__global__ __launch_bounds__(256, 2) void gemm_k(
    const __half* __restrict__ Ah, const __half* __restrict__ Am,
    const __half* __restrict__ Bh, const __half* __restrict__ Bm,
    float* __restrict__ C, int M, int N)
{
    extern __shared__ char smem[];
    const uint32_t sbase = smem_u32(smem);
    const int tid = threadIdx.x;
    const int wid = tid >> 5;
    const int lane = tid & 31;
    const int mBase = blockIdx.y * 128;
    const int nBase = blockIdx.x * 128;
    const int wm = (wid & 1) * 64;
    const int wn = (wid >> 1) * 32;
    const int NCHL = SPLITK ? (NCH / 2) : NCH;
    const int c0 = SPLITK ? blockIdx.z * NCHL : 0;

    const __half* srcs[4] = { Ah, Am, Bh, Bm };

    float acc[4][4][4];
#pragma unroll
    for (int i = 0; i < 4; i++)
#pragma unroll
        for (int j = 0; j < 4; j++)
#pragma unroll
            for (int q = 0; q < 4; q++) acc[i][j][q] = 0.f;

    // chunk loader: tiles {Ah[,Am],Bh[,Bm]} x 128 rows x 64 B
    auto load_chunk = [&](int c, int stage) {
        const uint32_t stBase = sbase + stage * STAGE4;
#pragma unroll
        for (int i = 0; i < 8; i++) {
            const int t = i >> 1;                   // tile 0..3 (uniform per i)
            if (MODE == 1 && (t == 1 || t == 3)) continue;   // only Ah, Bh
            const int idx = tid + i * 256;          // 0..2047
            const int r = (idx >> 2) & 127;         // row 0..127
            const int s = idx & 3;                  // 16B segment 0..3
            const int rb = ((t < 2) ? mBase : nBase) + r;
            const int bound = (t < 2) ? M : N;
            const uint32_t dst = stBase + t * TILEB + r * (TPADH * 2) + s * 16;
            const __half* src = srcs[t] + (size_t)rb * Dq + c * BKC + s * 8;
            cp16(dst, src, (rb < bound) ? 16u : 0u);
        }
        asm volatile("cp.async.commit_group;" ::: "memory");
    };

    load_chunk(c0, 0);

    for (int cc = 0; cc < NCHL; cc++) {
        if (cc + 1 < NCHL) {
            load_chunk(c0 + cc + 1, (cc + 1) & 1);
            asm volatile("cp.async.wait_group 1;" ::: "memory");
        } else {
            asm volatile("cp.async.wait_group 0;" ::: "memory");
        }
        __syncthreads();

        const char* st = smem + (cc & 1) * STAGE4;
        const __half* As_h = (const __half*)(st);
        const __half* As_m = (const __half*)(st + TILEB);
        const __half* Bs_h = (const __half*)(st + 2 * TILEB);
        const __half* Bs_m = (const __half*)(st + 3 * TILEB);

#pragma unroll
        for (int k16 = 0; k16 < BKC / 16; k16++) {
            const int kb = k16 * 16 + (lane & 3) * 2;
            uint32_t bh[4][2], bm[4][2];
#pragma unroll
            for (int nt = 0; nt < 4; nt++) {
                const int n = wn + nt * 8 + (lane >> 2);
                bh[nt][0] = *(const uint32_t*)&Bs_h[n * TPADH + kb];
                bh[nt][1] = *(const uint32_t*)&Bs_h[n * TPADH + kb + 8];
                if (MODE == 3) {
                    bm[nt][0] = *(const uint32_t*)&Bs_m[n * TPADH + kb];
                    bm[nt][1] = *(const uint32_t*)&Bs_m[n * TPADH + kb + 8];
                }
            }
#pragma unroll
            for (int mt = 0; mt < 4; mt++) {
                const int row = wm + mt * 16 + (lane >> 2);
                uint32_t ah[4], am[4];
                ah[0] = *(const uint32_t*)&As_h[row * TPADH + kb];
                ah[1] = *(const uint32_t*)&As_h[(row + 8) * TPADH + kb];
                ah[2] = *(const uint32_t*)&As_h[row * TPADH + kb + 8];
                ah[3] = *(const uint32_t*)&As_h[(row + 8) * TPADH + kb + 8];
                if (MODE == 3) {
                    am[0] = *(const uint32_t*)&As_m[row * TPADH + kb];
                    am[1] = *(const uint32_t*)&As_m[(row + 8) * TPADH + kb];
                    am[2] = *(const uint32_t*)&As_m[row * TPADH + kb + 8];
                    am[3] = *(const uint32_t*)&As_m[(row + 8) * TPADH + kb + 8];
                }
#pragma unroll
                for (int nt = 0; nt < 4; nt++) {
                    mma16816(acc[mt][nt], ah, bh[nt]);
                    if (MODE == 3) {
                        mma16816(acc[mt][nt], ah, bm[nt]);
                        mma16816(acc[mt][nt], am, bh[nt]);
                    }
                }
            }
        }
        __syncthreads();
    }

    // epilogue
#pragma unroll
    for (int mt = 0; mt < 4; mt++) {
        const int row0 = mBase + wm + mt * 16 + (lane >> 2);
#pragma unroll
        for (int nt = 0; nt < 4; nt++) {
            const int col0 = nBase + wn + nt * 8 + (lane & 3) * 2;
            if (col0 < N) {
                if (SPLITK) {   // exactly 2 partials per element -> commutative, deterministic
                    if (row0 < M) {
                        atomicAdd(&C[(size_t)row0 * N + col0], acc[mt][nt][0]);
                        atomicAdd(&C[(size_t)row0 * N + col0 + 1], acc[mt][nt][1]);
                    }
                    if (row0 + 8 < M) {
                        atomicAdd(&C[(size_t)(row0 + 8) * N + col0], acc[mt][nt][2]);
                        atomicAdd(&C[(size_t)(row0 + 8) * N + col0 + 1], acc[mt][nt][3]);
                    }
                } else {
                    if (row0 < M)
                        *(float2*)&C[(size_t)row0 * N + col0] =
                            make_float2(acc[mt][nt][0], acc[mt][nt][1]);
                    if (row0 + 8 < M)
                        *(float2*)&C[(size_t)(row0 + 8) * N + col0] =
                            make_float2(acc[mt][nt][2], acc[mt][nt][3]);
                }
            }
        }
    }
}

// -- fused: split fp32 -> 2 fp16 limbs + inv L2 norm + zero P and class counters --
__global__ __launch_bounds__(NTHR) void split_norm(
    const float* __restrict__ z, const float* __restrict__ W,
    __half* __restrict__ Ah, __half* __restrict__ Am, float* __restrict__ invn,
    float* __restrict__ P, int* __restrict__ cnt)
{
    const int r = blockIdx.x;   // support index: [0,Cq) = W, [Cq,Nsup) = z
    const float* src = (r < Cq) ? (W + (size_t)r * Dq) : (z + (size_t)(r - Cq) * Dq);
    const int tid = threadIdx.x;

    // zero this row of P (1000 floats = 250 float4) and, from block 0, the counters
    if (tid < 250) ((float4*)(P + (size_t)r * Cq))[tid] = make_float4(0.f, 0.f, 0.f, 0.f);
    if (r == 0) for (int i = tid; i < Cq; i += NTHR) cnt[i] = 0;

    float ss = 0.f;
    const float4* src4 = (const float4*)src;
#pragma unroll
    for (int j = 0; j < Dq / (NTHR * 4); j++) {
        const int i4 = tid + j * NTHR;
        float4 x = src4[i4];
        const int i = i4 * 4;
        __half h0 = __float2half_rn(x.x), h1 = __float2half_rn(x.y);
        __half h2 = __float2half_rn(x.z), h3 = __float2half_rn(x.w);
        Ah[(size_t)r * Dq + i + 0] = h0; Ah[(size_t)r * Dq + i + 1] = h1;
        Ah[(size_t)r * Dq + i + 2] = h2; Ah[(size_t)r * Dq + i + 3] = h3;
        Am[(size_t)r * Dq + i + 0] = __float2half_rn(x.x - __half2float(h0));
        Am[(size_t)r * Dq + i + 1] = __float2half_rn(x.y - __half2float(h1));
        Am[(size_t)r * Dq + i + 2] = __float2half_rn(x.z - __half2float(h2));
        Am[(size_t)r * Dq + i + 3] = __float2half_rn(x.w - __half2float(h3));
        ss += x.x * x.x + x.y * x.y + x.z * x.z + x.w * x.w;
    }
    __shared__ float red[NTHR];
    red[tid] = ss; __syncthreads();
    for (int s = NTHR / 2; s > 0; s >>= 1) {
        if (tid < s) red[tid] += red[tid + s];
        __syncthreads();
    }
    if (tid == 0) invn[r] = 1.0f / fmaxf(sqrtf(red[0]), 1e-12f);
}

// -- single-pass entropy + argmax (logits held in registers) + bucket scatter ----
__global__ __launch_bounds__(NTHR) void row_entropy_scatter(
    const float* __restrict__ P, float* __restrict__ ent,
    int* __restrict__ cnt, float* __restrict__ bktE, int* __restrict__ bktI)
{
    const int row = blockIdx.x;
    const int tid = threadIdx.x;
    __shared__ float sm[NTHR];
    __shared__ int   si[NTHR];

    // each thread owns 4 logits (250 float4 cover the row; tid>=250 idle)
    float4 v = make_float4(-FLT_MAX, -FLT_MAX, -FLT_MAX, -FLT_MAX);
    if (tid < 250) v = ((const float4*)(P + (size_t)row * Cq))[tid];

    float m = v.x; int mi = tid * 4;
    if (v.y > m) { m = v.y; mi = tid * 4 + 1; }
    if (v.z > m) { m = v.z; mi = tid * 4 + 2; }
    if (v.w > m) { m = v.w; mi = tid * 4 + 3; }
    sm[tid] = m; si[tid] = (tid < 250) ? mi : 0x7fffffff;
    __syncthreads();
    for (int s = NTHR / 2; s > 0; s >>= 1) {
        if (tid < s) {
            float m2 = sm[tid + s]; int i2 = si[tid + s];
            if (m2 > sm[tid] || (m2 == sm[tid] && i2 < si[tid])) { sm[tid] = m2; si[tid] = i2; }
        }
        __syncthreads();
    }
    const float rowmax = sm[0];
    const int rowarg = si[0];
    __syncthreads();

    float s1 = 0.f, s2 = 0.f;
    if (tid < 250) {
        float d0 = v.x - rowmax, d1 = v.y - rowmax, d2 = v.z - rowmax, d3 = v.w - rowmax;
        float e0 = expf(d0), e1 = expf(d1), e2 = expf(d2), e3 = expf(d3);
        s1 = e0 + e1 + e2 + e3;
        s2 = e0 * d0 + e1 * d1 + e2 * d2 + e3 * d3;
    }
    sm[tid] = s1; __syncthreads();
    for (int s = NTHR / 2; s > 0; s >>= 1) { if (tid < s) sm[tid] += sm[tid + s]; __syncthreads(); }
    s1 = sm[0]; __syncthreads();
    sm[tid] = s2; __syncthreads();
    for (int s = NTHR / 2; s > 0; s >>= 1) { if (tid < s) sm[tid] += sm[tid + s]; __syncthreads(); }
    s2 = sm[0];

    if (tid == 0) {
        float e = logf(s1) - s2 / s1;
        ent[row] = e;
        int pos = atomicAdd(&cnt[rowarg], 1);
        bktE[(size_t)rowarg * BCAP + pos] = e;
        bktI[(size_t)rowarg * BCAP + pos] = row;
    }
}

// ---- per-class: K smallest entropies from bucket, ascending (ent, idx) order ---
__global__ __launch_bounds__(NTHR) void select_topk(
    const int* __restrict__ cnt, const float* __restrict__ bktE,
    const int* __restrict__ bktI, const int* __restrict__ pK,
    int* __restrict__ selidx, int* __restrict__ selcnt)
{
    __shared__ float se[BCAP];
    __shared__ int   sidx[BCAP];
    __shared__ float rbv[NTHR];
    __shared__ int   rbk[NTHR];
    __shared__ int   rbp[NTHR];

    const int c = blockIdx.x;
    int K = *pK; if (K > KMAX) K = KMAX;
    const int n = cnt[c];
    const int take = (n < K) ? n : K;

    for (int i = threadIdx.x; i < n; i += NTHR) {
        se[i] = bktE[(size_t)c * BCAP + i];
        sidx[i] = bktI[(size_t)c * BCAP + i];
    }
    __syncthreads();

    // min-extraction: emits ascending (ent, idx) — deterministic and matches top_k
    for (int t = 0; t < take; t++) {
        float bv = FLT_MAX; int bk = 0x7fffffff; int bp = -1;
        for (int i = threadIdx.x; i < n; i += NTHR) {
            float v = se[i]; int key = sidx[i];
            if (v < bv || (v == bv && key < bk)) { bv = v; bk = key; bp = i; }
        }
        rbv[threadIdx.x] = bv; rbk[threadIdx.x] = bk; rbp[threadIdx.x] = bp;
        __syncthreads();
        for (int s = NTHR / 2; s > 0; s >>= 1) {
            if (threadIdx.x < s) {
                float v2 = rbv[threadIdx.x + s]; int k2 = rbk[threadIdx.x + s];
                if (v2 < rbv[threadIdx.x] ||
                    (v2 == rbv[threadIdx.x] && k2 < rbk[threadIdx.x])) {
                    rbv[threadIdx.x] = v2; rbk[threadIdx.x] = k2;
                    rbp[threadIdx.x] = rbp[threadIdx.x + s];
                }
            }
            __syncthreads();
        }
        if (threadIdx.x == 0) {
            int p = rbp[0];
            selidx[c * KMAX + t] = sidx[p];
            se[p] = FLT_MAX;
        }
        __syncthreads();
    }
    if (threadIdx.x == 0) selcnt[c] = take;
}

// ----- build normalized prototypes, emit fp16 high limb of weights^T ------------
__global__ __launch_bounds__(NTHR) void build_weights(
    const float* __restrict__ W, const float* __restrict__ z,
    const float* __restrict__ invn, const int* __restrict__ selidx,
    const int* __restrict__ selcnt, __half* __restrict__ Th)
{
    const int c = blockIdx.x;
    const int n = selcnt[c];
    const int tid = threadIdx.x;
    float acc[Dq / NTHR];
#pragma unroll
    for (int j = 0; j < Dq / NTHR; j++) acc[j] = 0.f;

    for (int t = 0; t < n; t++) {
        int idx = selidx[c * KMAX + t];
        float s = invn[idx];
        const float* row = (idx < Cq) ? (W + (size_t)idx * Dq) : (z + (size_t)(idx - Cq) * Dq);
#pragma unroll
        for (int j = 0; j < Dq / NTHR; j++) acc[j] += s * row[tid + j * NTHR];
    }

    float ss = 0.f;
#pragma unroll
    for (int j = 0; j < Dq / NTHR; j++) ss += acc[j] * acc[j];
    __shared__ float red[NTHR];
    red[tid] = ss; __syncthreads();
    for (int s = NTHR / 2; s > 0; s >>= 1) {
        if (tid < s) red[tid] += red[tid + s];
        __syncthreads();
    }
    const float inv = 1.0f / fmaxf(sqrtf(red[0]), 1e-12f);
#pragma unroll
    for (int j = 0; j < Dq / NTHR; j++)
        Th[(size_t)c * Dq + tid + j * NTHR] = __float2half_rn(acc[j] * inv);
}

// --------------------------------- launch ---------------------------------------
extern "C" void kernel_launch(void* const* d_in, const int* in_sizes, int n_in,
                              void* d_out, int out_size)
{
    const float* z = (const float*)d_in[0];
    const float* W = (const float*)d_in[1];
    const int* pK  = (const int*)d_in[2];
    float* out = (float*)d_out;

    float *P, *ent, *invn, *bktE;
    int *cnt, *bktI, *selidx, *selcnt;
    __half *Ah, *Am, *Th;
    cudaGetSymbolAddress((void**)&P, g_P);
    cudaGetSymbolAddress((void**)&ent, g_ent);
    cudaGetSymbolAddress((void**)&invn, g_invn);
    cudaGetSymbolAddress((void**)&cnt, g_cnt);
    cudaGetSymbolAddress((void**)&bktE, g_bktE);
    cudaGetSymbolAddress((void**)&bktI, g_bktI);
    cudaGetSymbolAddress((void**)&selidx, g_selidx);
    cudaGetSymbolAddress((void**)&selcnt, g_selcnt);
    cudaGetSymbolAddress((void**)&Ah, g_Ah);
    cudaGetSymbolAddress((void**)&Am, g_Am);
    cudaGetSymbolAddress((void**)&Th, g_Th);

    cudaFuncSetAttribute((const void*)gemm_k<3, true>,
                         cudaFuncAttributeMaxDynamicSharedMemorySize, GSMEM);
    cudaFuncSetAttribute((const void*)gemm_k<1, false>,
                         cudaFuncAttributeMaxDynamicSharedMemorySize, GSMEM);

    // 0) limb split of [W; z], inverse norms, zero P + counters
    split_norm<<<Nsup, NTHR>>>(z, W, Ah, Am, invn, P, cnt);

    // 1) merged logits: P[5096,1000] = [W;z] @ W^T  (3-pair, split-K=2, atomic)
    gemm_k<3, true><<<dim3(8, 40, 2), 256, GSMEM>>>(Ah, Am, Ah, Am, P, Nsup, Cq);

    // 2) entropy + argmax + per-class bucket scatter
    row_entropy_scatter<<<Nsup, NTHR>>>(P, ent, cnt, bktE, bktI);

    // 3) per-class selection from buckets
    select_topk<<<Cq, NTHR>>>(cnt, bktE, bktI, pK, selidx, selcnt);

    // 4) prototypes (fp16 high limb only)
    build_weights<<<Cq, NTHR>>>(W, z, invn, selidx, selcnt, Th);

    // 5) out = z @ weights   (single-pair fp16)
    gemm_k<1, false><<<dim3(8, 32), 256, GSMEM>>>(Ah + (size_t)Cq * Dq, Am + (size_t)Cq * Dq,
                                                  Th, Th, out, Bq, Cq);
}

// round 10
// speedup vs baseline: 3.9852x; 1.1448x over previous
#include <cuda_runtime.h>
#include <cuda_fp16.h>
#include <math.h>
#include <float.h>
#include <stdint.h>

// Problem-fixed shapes: z [B,D], W [C,D], out [B,C]
#define Bq 4096
#define Dq 2048
#define Cq 1000
#define Nsup (Bq + Cq)   // 5096, supports ordered [W; z]
#define KMAX 128
#define NTHR 256
#define BCAP 5096        // per-class bucket capacity (worst case)

// ---------------- scratch (static device globals; no allocation) ----------------
__device__ float g_P[Nsup * Cq];          // 20.4 MB merged logits (split-K accum)
__device__ float g_ent[Nsup];
__device__ float g_invn[Nsup];
__device__ int   g_cnt[Cq];
__device__ float g_bktE[Cq * BCAP];       // per-class entropy buckets
__device__ int   g_bktI[Cq * BCAP];
__device__ int   g_selidx[Cq * KMAX];
__device__ int   g_selcnt[Cq];
__device__ __half g_Ah[Nsup * Dq], g_Am[Nsup * Dq];   // fp16 limb splits of [W; z]
__device__ __half g_Th[Cq * Dq];                      // fp16 high limb of weights^T

// ==================== mma.sync fp16 multi-pair GEMM (C = A*B^T) =================
// MODE 3: C = Ah*Bh^T + Ah*Bm^T + Am*Bh^T   (logits, ~fp32 accuracy)
// MODE 1: C = Ah*Bh^T                        (final, both operands single-limb)
#define BKC   32                       // K per chunk
#define NCH   (Dq / BKC)               // 64
#define TPADH 40                       // padded half-stride: 80 B rows, conflict-free
#define TROWB (TPADH * 2)              // 80 B per row
#define TILEB (128 * TROWB)            // 10240 B
#define STAGE4 (4 * TILEB)             // 40960 B (Ah, Am, Bh, Bm)
#define GSMEM (2 * STAGE4)             // 81920 B -> 2 CTAs/SM

__device__ __forceinline__ uint32_t smem_u32(const void* p) {
    uint32_t a;
    asm("{ .reg .u64 t; cvta.to.shared.u64 t, %1; cvt.u32.u64 %0, t; }" : "=r"(a) : "l"(p));
    return a;
}
__device__ __forceinline__ void cp16(uint32_t dst, const void* src, uint32_t srcsize) {
    asm volatile("cp.async.cg.shared.global [%0], [%1], 16, %2;"
                 :: "r"(dst), "l"(src), "r"(srcsize) : "memory");
}
__device__ __forceinline__ void mma16816(float* c, const uint32_t* a, const uint32_t* b) {
    asm volatile("mma.sync.aligned.m16n8k16.row.col.f32.f16.f16.f32 "
                 "{%0,%1,%2,%3}, {%4,%5,%6,%7}, {%8,%9}, {%0,%1,%2,%3};"
                 : "+f"(c[0]), "+f"(c[1]), "+f"(c[2]), "+f"(c[3])
                 : "r"(a[0]), "r"(a[1]), "r"(a[2]), "r"(a[3]), "r"(b[0]), "r"(b[1]));
}
__device__ __forceinline__ void ldsm4(uint32_t* r, uint32_t addr) {
    asm volatile("ldmatrix.sync.aligned.m8n8.x4.shared.b16 {%0,%1,%2,%3}, [%4];"
                 : "=r"(r[0]), "=r"(r[1]), "=r"(r[2]), "=r"(r[3]) : "r"(addr));
}

template<int MODE, bool SPLITK>
__global__ __launch_bounds__(256, 2) void gemm_k(
    const __half* __restrict__ Ah, const __half* __restrict__ Am,
    const __half* __restrict__ Bh, const __half* __restrict__ Bm,
    float* __restrict__ C, int M, int N)
{
    extern __shared__ char smem[];
    const uint32_t sbase = smem_u32(smem);
    const int tid = threadIdx.x;
    const int wid = tid >> 5;
    const int lane = tid & 31;
    const int mBase = blockIdx.y * 128;
    const int nBase = blockIdx.x * 128;
    const int wm = (wid & 1) * 64;
    const int wn = (wid >> 1) * 32;
    const int NCHL = SPLITK ? (NCH / 2) : NCH;
    const int c0 = SPLITK ? blockIdx.z * NCHL : 0;

    const __half* srcs[4] = { Ah, Am, Bh, Bm };

    // ldmatrix lane->address components (byte offsets within a tile)
    const int aRow = lane & 15;                         // rows 0..15 of m16 tile
    const int aKB  = (lane >> 4) * 16;                  // +8 halves = +16 B for k8-15
    const int bG   = lane >> 3;
    const int bRow = (lane & 7) + ((bG >> 1) << 3);     // rows 0..15 of n16 pair
    const int bKB  = (bG & 1) * 16;

    float acc[4][4][4];
#pragma unroll
    for (int i = 0; i < 4; i++)
#pragma unroll
        for (int j = 0; j < 4; j++)
#pragma unroll
            for (int q = 0; q < 4; q++) acc[i][j][q] = 0.f;

    // chunk loader: tiles {Ah[,Am],Bh[,Bm]} x 128 rows x 64 B
    auto load_chunk = [&](int c, int stage) {
        const uint32_t stBase = sbase + stage * STAGE4;
#pragma unroll
        for (int i = 0; i < 8; i++) {
            const int t = i >> 1;                   // tile 0..3 (uniform per i)
            if (MODE == 1 && (t == 1 || t == 3)) continue;   // only Ah, Bh
            const int idx = tid + i * 256;          // 0..2047
            const int r = (idx >> 2) & 127;         // row 0..127
            const int s = idx & 3;                  // 16B segment 0..3
            const int rb = ((t < 2) ? mBase : nBase) + r;
            const int bound = (t < 2) ? M : N;
            const uint32_t dst = stBase + t * TILEB + r * TROWB + s * 16;
            const __half* src = srcs[t] + (size_t)rb * Dq + c * BKC + s * 8;
            cp16(dst, src, (rb < bound) ? 16u : 0u);
        }
        asm volatile("cp.async.commit_group;" ::: "memory");
    };

    load_chunk(c0, 0);

    for (int cc = 0; cc < NCHL; cc++) {
        if (cc + 1 < NCHL) {
            load_chunk(c0 + cc + 1, (cc + 1) & 1);
            asm volatile("cp.async.wait_group 1;" ::: "memory");
        } else {
            asm volatile("cp.async.wait_group 0;" ::: "memory");
        }
        __syncthreads();

        const uint32_t st = sbase + (cc & 1) * STAGE4;
        const uint32_t aH = st;
        const uint32_t aM = st + TILEB;
        const uint32_t bH = st + 2 * TILEB;
        const uint32_t bM = st + 3 * TILEB;

#pragma unroll
        for (int k16 = 0; k16 < BKC / 16; k16++) {
            const int kOff = k16 * 32;              // 16 halves = 32 B
            uint32_t bh[4][2], bm[4][2];
#pragma unroll
            for (int p = 0; p < 2; p++) {           // two n16 pairs cover nt 0..3
                const uint32_t bOff = (uint32_t)(wn + p * 16 + bRow) * TROWB + kOff + bKB;
                ldsm4(&bh[p * 2][0], bH + bOff);
                if (MODE == 3) ldsm4(&bm[p * 2][0], bM + bOff);
            }
#pragma unroll
            for (int mt = 0; mt < 4; mt++) {
                const uint32_t aOff = (uint32_t)(wm + mt * 16 + aRow) * TROWB + kOff + aKB;
                uint32_t ah[4], am[4];
                ldsm4(ah, aH + aOff);
                if (MODE == 3) ldsm4(am, aM + aOff);
#pragma unroll
                for (int nt = 0; nt < 4; nt++) {
                    mma16816(acc[mt][nt], ah, bh[nt]);
                    if (MODE == 3) {
                        mma16816(acc[mt][nt], ah, bm[nt]);
                        mma16816(acc[mt][nt], am, bh[nt]);
                    }
                }
            }
        }
        __syncthreads();
    }

    // epilogue
#pragma unroll
    for (int mt = 0; mt < 4; mt++) {
        const int row0 = mBase + wm + mt * 16 + (lane >> 2);
#pragma unroll
        for (int nt = 0; nt < 4; nt++) {
            const int col0 = nBase + wn + nt * 8 + (lane & 3) * 2;
            if (col0 < N) {
                if (SPLITK) {   // exactly 2 partials per element -> commutative, deterministic
                    if (row0 < M) {
                        atomicAdd(&C[(size_t)row0 * N + col0], acc[mt][nt][0]);
                        atomicAdd(&C[(size_t)row0 * N + col0 + 1], acc[mt][nt][1]);
                    }
                    if (row0 + 8 < M) {
                        atomicAdd(&C[(size_t)(row0 + 8) * N + col0], acc[mt][nt][2]);
                        atomicAdd(&C[(size_t)(row0 + 8) * N + col0 + 1], acc[mt][nt][3]);
                    }
                } else {
                    if (row0 < M)
                        *(float2*)&C[(size_t)row0 * N + col0] =
                            make_float2(acc[mt][nt][0], acc[mt][nt][1]);
                    if (row0 + 8 < M)
                        *(float2*)&C[(size_t)(row0 + 8) * N + col0] =
                            make_float2(acc[mt][nt][2], acc[mt][nt][3]);
                }
            }
        }
    }
}

// -- fused: split fp32 -> 2 fp16 limbs + inv L2 norm + zero P and class counters --
__global__ __launch_bounds__(NTHR) void split_norm(
    const float* __restrict__ z, const float* __restrict__ W,
    __half* __restrict__ Ah, __half* __restrict__ Am, float* __restrict__ invn,
    float* __restrict__ P, int* __restrict__ cnt)
{
    const int r = blockIdx.x;   // support index: [0,Cq) = W, [Cq,Nsup) = z
    const float* src = (r < Cq) ? (W + (size_t)r * Dq) : (z + (size_t)(r - Cq) * Dq);
    const int tid = threadIdx.x;

    // zero this row of P (1000 floats = 250 float4) and, from block 0, the counters
    if (tid < 250) ((float4*)(P + (size_t)r * Cq))[tid] = make_float4(0.f, 0.f, 0.f, 0.f);
    if (r == 0) for (int i = tid; i < Cq; i += NTHR) cnt[i] = 0;

    float ss = 0.f;
    const float4* src4 = (const float4*)src;
#pragma unroll
    for (int j = 0; j < Dq / (NTHR * 4); j++) {
        const int i4 = tid + j * NTHR;
        float4 x = src4[i4];
        const int i = i4 * 4;
        __half h0 = __float2half_rn(x.x), h1 = __float2half_rn(x.y);
        __half h2 = __float2half_rn(x.z), h3 = __float2half_rn(x.w);
        Ah[(size_t)r * Dq + i + 0] = h0; Ah[(size_t)r * Dq + i + 1] = h1;
        Ah[(size_t)r * Dq + i + 2] = h2; Ah[(size_t)r * Dq + i + 3] = h3;
        Am[(size_t)r * Dq + i + 0] = __float2half_rn(x.x - __half2float(h0));
        Am[(size_t)r * Dq + i + 1] = __float2half_rn(x.y - __half2float(h1));
        Am[(size_t)r * Dq + i + 2] = __float2half_rn(x.z - __half2float(h2));
        Am[(size_t)r * Dq + i + 3] = __float2half_rn(x.w - __half2float(h3));
        ss += x.x * x.x + x.y * x.y + x.z * x.z + x.w * x.w;
    }
    __shared__ float red[NTHR];
    red[tid] = ss; __syncthreads();
    for (int s = NTHR / 2; s > 0; s >>= 1) {
        if (tid < s) red[tid] += red[tid + s];
        __syncthreads();
    }
    if (tid == 0) invn[r] = 1.0f / fmaxf(sqrtf(red[0]), 1e-12f);
}

// -- single-pass entropy + argmax (logits held in registers) + bucket scatter ----
__global__ __launch_bounds__(NTHR) void row_entropy_scatter(
    const float* __restrict__ P, float* __restrict__ ent,
    int* __restrict__ cnt, float* __restrict__ bktE, int* __restrict__ bktI)
{
    const int row = blockIdx.x;
    const int tid = threadIdx.x;
    __shared__ float sm[NTHR];
    __shared__ int   si[NTHR];

    // each thread owns 4 logits (250 float4 cover the row; tid>=250 idle)
    float4 v = make_float4(-FLT_MAX, -FLT_MAX, -FLT_MAX, -FLT_MAX);
    if (tid < 250) v = ((const float4*)(P + (size_t)row * Cq))[tid];

    float m = v.x; int mi = tid * 4;
    if (v.y > m) { m = v.y; mi = tid * 4 + 1; }
    if (v.z > m) { m = v.z; mi = tid * 4 + 2; }
    if (v.w > m) { m = v.w; mi = tid * 4 + 3; }
    sm[tid] = m; si[tid] = (tid < 250) ? mi : 0x7fffffff;
    __syncthreads();
    for (int s = NTHR / 2; s > 0; s >>= 1) {
        if (tid < s) {
            float m2 = sm[tid + s]; int i2 = si[tid + s];
            if (m2 > sm[tid] || (m2 == sm[tid] && i2 < si[tid])) { sm[tid] = m2; si[tid] = i2; }
        }
        __syncthreads();
    }
    const float rowmax = sm[0];
    const int rowarg = si[0];
    __syncthreads();

    float s1 = 0.f, s2 = 0.f;
    if (tid < 250) {
        float d0 = v.x - rowmax, d1 = v.y - rowmax, d2 = v.z - rowmax, d3 = v.w - rowmax;
        float e0 = expf(d0), e1 = expf(d1), e2 = expf(d2), e3 = expf(d3);
        s1 = e0 + e1 + e2 + e3;
        s2 = e0 * d0 + e1 * d1 + e2 * d2 + e3 * d3;
    }
    sm[tid] = s1; __syncthreads();
    for (int s = NTHR / 2; s > 0; s >>= 1) { if (tid < s) sm[tid] += sm[tid + s]; __syncthreads(); }
    s1 = sm[0]; __syncthreads();
    sm[tid] = s2; __syncthreads();
    for (int s = NTHR / 2; s > 0; s >>= 1) { if (tid < s) sm[tid] += sm[tid + s]; __syncthreads(); }
    s2 = sm[0];

    if (tid == 0) {
        float e = logf(s1) - s2 / s1;
        ent[row] = e;
        int pos = atomicAdd(&cnt[rowarg], 1);
        bktE[(size_t)rowarg * BCAP + pos] = e;
        bktI[(size_t)rowarg * BCAP + pos] = row;
    }
}

// ---- per-class K smallest, warp-per-class, no mutation (ascending emit) --------
__global__ __launch_bounds__(NTHR) void select_topk(
    const int* __restrict__ cnt, const float* __restrict__ bktE,
    const int* __restrict__ bktI, const int* __restrict__ pK,
    int* __restrict__ selidx, int* __restrict__ selcnt)
{
    const int c = blockIdx.x * (NTHR / 32) + (threadIdx.x >> 5);
    if (c >= Cq) return;
    const int lane = threadIdx.x & 31;
    int K = *pK; if (K > KMAX) K = KMAX;
    const int n = cnt[c];
    const int take = (n < K) ? n : K;
    const float* E = bktE + (size_t)c * BCAP;
    const int*   I = bktI + (size_t)c * BCAP;

    float prevE = -FLT_MAX; int prevI = -1;
    for (int t = 0; t < take; t++) {
        // min over entries strictly greater (lex) than (prevE, prevI)
        float bv = FLT_MAX; int bk = 0x7fffffff;
        for (int i = lane; i < n; i += 32) {
            float v = E[i]; int key = I[i];
            bool gt_prev = (v > prevE) || (v == prevE && key > prevI);
            if (gt_prev && (v < bv || (v == bv && key < bk))) { bv = v; bk = key; }
        }
#pragma unroll
        for (int o = 16; o > 0; o >>= 1) {
            float v2 = __shfl_down_sync(0xffffffffu, bv, o);
            int   k2 = __shfl_down_sync(0xffffffffu, bk, o);
            if (v2 < bv || (v2 == bv && k2 < bk)) { bv = v2; bk = k2; }
        }
        bv = __shfl_sync(0xffffffffu, bv, 0);
        bk = __shfl_sync(0xffffffffu, bk, 0);
        if (lane == 0) selidx[c * KMAX + t] = bk;
        prevE = bv; prevI = bk;
    }
    if (lane == 0) selcnt[c] = take;
}

// ----- build normalized prototypes, emit fp16 high limb of weights^T ------------
__global__ __launch_bounds__(NTHR) void build_weights(
    const float* __restrict__ W, const float* __restrict__ z,
    const float* __restrict__ invn, const int* __restrict__ selidx,
    const int* __restrict__ selcnt, __half* __restrict__ Th)
{
    const int c = blockIdx.x;
    const int n = selcnt[c];
    const int tid = threadIdx.x;
    float acc[Dq / NTHR];
#pragma unroll
    for (int j = 0; j < Dq / NTHR; j++) acc[j] = 0.f;

    for (int t = 0; t < n; t++) {
        int idx = selidx[c * KMAX + t];
        float s = invn[idx];
        const float* row = (idx < Cq) ? (W + (size_t)idx * Dq) : (z + (size_t)(idx - Cq) * Dq);
#pragma unroll
        for (int j = 0; j < Dq / NTHR; j++) acc[j] += s * row[tid + j * NTHR];
    }

    float ss = 0.f;
#pragma unroll
    for (int j = 0; j < Dq / NTHR; j++) ss += acc[j] * acc[j];
    __shared__ float red[NTHR];
    red[tid] = ss; __syncthreads();
    for (int s = NTHR / 2; s > 0; s >>= 1) {
        if (tid < s) red[tid] += red[tid + s];
        __syncthreads();
    }
    const float inv = 1.0f / fmaxf(sqrtf(red[0]), 1e-12f);
#pragma unroll
    for (int j = 0; j < Dq / NTHR; j++)
        Th[(size_t)c * Dq + tid + j * NTHR] = __float2half_rn(acc[j] * inv);
}

// --------------------------------- launch ---------------------------------------
extern "C" void kernel_launch(void* const* d_in, const int* in_sizes, int n_in,
                              void* d_out, int out_size)
{
    const float* z = (const float*)d_in[0];
    const float* W = (const float*)d_in[1];
    const int* pK  = (const int*)d_in[2];
    float* out = (float*)d_out;

    float *P, *ent, *invn, *bktE;
    int *cnt, *bktI, *selidx, *selcnt;
    __half *Ah, *Am, *Th;
    cudaGetSymbolAddress((void**)&P, g_P);
    cudaGetSymbolAddress((void**)&ent, g_ent);
    cudaGetSymbolAddress((void**)&invn, g_invn);
    cudaGetSymbolAddress((void**)&cnt, g_cnt);
    cudaGetSymbolAddress((void**)&bktE, g_bktE);
    cudaGetSymbolAddress((void**)&bktI, g_bktI);
    cudaGetSymbolAddress((void**)&selidx, g_selidx);
    cudaGetSymbolAddress((void**)&selcnt, g_selcnt);
    cudaGetSymbolAddress((void**)&Ah, g_Ah);
    cudaGetSymbolAddress((void**)&Am, g_Am);
    cudaGetSymbolAddress((void**)&Th, g_Th);

    cudaFuncSetAttribute((const void*)gemm_k<3, true>,
                         cudaFuncAttributeMaxDynamicSharedMemorySize, GSMEM);
    cudaFuncSetAttribute((const void*)gemm_k<1, false>,
                         cudaFuncAttributeMaxDynamicSharedMemorySize, GSMEM);

    // 0) limb split of [W; z], inverse norms, zero P + counters
    split_norm<<<Nsup, NTHR>>>(z, W, Ah, Am, invn, P, cnt);

    // 1) merged logits: P[5096,1000] = [W;z] @ W^T  (3-pair, split-K=2, atomic)
    gemm_k<3, true><<<dim3(8, 40, 2), 256, GSMEM>>>(Ah, Am, Ah, Am, P, Nsup, Cq);

    // 2) entropy + argmax + per-class bucket scatter
    row_entropy_scatter<<<Nsup, NTHR>>>(P, ent, cnt, bktE, bktI);

    // 3) per-class selection (warp per class, read-only, ascending emit)
    select_topk<<<(Cq + (NTHR / 32) - 1) / (NTHR / 32), NTHR>>>(cnt, bktE, bktI, pK,
                                                               selidx, selcnt);

    // 4) prototypes (fp16 high limb only)
    build_weights<<<Cq, NTHR>>>(W, z, invn, selidx, selcnt, Th);

    // 5) out = z @ weights   (single-pair fp16)
    gemm_k<1, false><<<dim3(8, 32), 256, GSMEM>>>(Ah + (size_t)Cq * Dq, Am + (size_t)Cq * Dq,
                                                  Th, Th, out, Bq, Cq);
}

// round 13
// speedup vs baseline: 4.1207x; 1.0340x over previous
#include <cuda_runtime.h>
#include <cuda_fp16.h>
#include <math.h>
#include <float.h>
#include <stdint.h>

// Problem-fixed shapes: z [B,D], W [C,D], out [B,C]
#define Bq 4096
#define Dq 2048
#define Cq 1000
#define Nsup (Bq + Cq)   // 5096, supports ordered [W; z]
#define KMAX 128
#define NTHR 256
#define BCAP 5096        // per-class bucket capacity (worst case)
#define PSZ ((size_t)Nsup * Cq)

// ---------------- scratch (static device globals; no allocation) ----------------
__device__ float g_P[2 * Nsup * Cq];      // 40.8 MB: two split-K partial buffers
__device__ float g_invn[Nsup];
__device__ int   g_cnt[Cq];
__device__ float g_bktE[Cq * BCAP];       // per-class entropy buckets
__device__ int   g_bktI[Cq * BCAP];
__device__ int   g_selidx[Cq * KMAX];
__device__ int   g_selcnt[Cq];
__device__ __half g_Ah[Nsup * Dq], g_Am[Nsup * Dq];   // fp16 limb splits of [W; z]
__device__ __half g_Th[Cq * Dq];                      // fp16 high limb of weights^T

// ==================== mma.sync fp16 multi-pair GEMM (C = A*B^T) =================
// MODE 3: C = Ah*Bh^T + Ah*Bm^T + Am*Bh^T   (logits, ~fp32 accuracy)
// MODE 1: C = Ah*Bh^T                        (final, both operands single-limb)
#define BKC   32                       // K per chunk
#define NCH   (Dq / BKC)               // 64
#define TPADH 40                       // padded half-stride: 80 B rows, conflict-free
#define TROWB (TPADH * 2)              // 80 B per row
#define TILEB (128 * TROWB)            // 10240 B
#define STAGE4 (4 * TILEB)             // 40960 B (Ah, Am, Bh, Bm)
#define GSMEM (2 * STAGE4)             // 81920 B -> 2 CTAs/SM

__device__ __forceinline__ uint32_t smem_u32(const void* p) {
    uint32_t a;
    asm("{ .reg .u64 t; cvta.to.shared.u64 t, %1; cvt.u32.u64 %0, t; }" : "=r"(a) : "l"(p));
    return a;
}
__device__ __forceinline__ void cp16(uint32_t dst, const void* src, uint32_t srcsize) {
    asm volatile("cp.async.cg.shared.global [%0], [%1], 16, %2;"
                 :: "r"(dst), "l"(src), "r"(srcsize) : "memory");
}
__device__ __forceinline__ void mma16816(float* c, const uint32_t* a, const uint32_t* b) {
    asm volatile("mma.sync.aligned.m16n8k16.row.col.f32.f16.f16.f32 "
                 "{%0,%1,%2,%3}, {%4,%5,%6,%7}, {%8,%9}, {%0,%1,%2,%3};"
                 : "+f"(c[0]), "+f"(c[1]), "+f"(c[2]), "+f"(c[3])
                 : "r"(a[0]), "r"(a[1]), "r"(a[2]), "r"(a[3]), "r"(b[0]), "r"(b[1]));
}
__device__ __forceinline__ void ldsm4(uint32_t* r, uint32_t addr) {
    asm volatile("ldmatrix.sync.aligned.m8n8.x4.shared.b16 {%0,%1,%2,%3}, [%4];"
                 : "=r"(r[0]), "=r"(r[1]), "=r"(r[2]), "=r"(r[3]) : "r"(addr));
}

template<int MODE, bool SPLITK>
__global__ __launch_bounds__(256, 2) void gemm_k(
    const __half* __restrict__ Ah, const __half* __restrict__ Am,
    const __half* __restrict__ Bh, const __half* __restrict__ Bm,
    float* __restrict__ C, int M, int N)
{
    extern __shared__ char smem[];
    const uint32_t sbase = smem_u32(smem);
    const int tid = threadIdx.x;
    const int wid = tid >> 5;
    const int lane = tid & 31;
    const int mBase = blockIdx.y * 128;
    const int nBase = blockIdx.x * 128;
    const int wm = (wid & 1) * 64;
    const int wn = (wid >> 1) * 32;
    const int NCHL = SPLITK ? (NCH / 2) : NCH;
    const int c0 = SPLITK ? blockIdx.z * NCHL : 0;
    if (SPLITK) C += (size_t)blockIdx.z * PSZ;     // per-half partial buffer

    const __half* srcs[4] = { Ah, Am, Bh, Bm };

    // ldmatrix lane->address components (byte offsets within a tile)
    const int aRow = lane & 15;                         // rows 0..15 of m16 tile
    const int aKB  = (lane >> 4) * 16;                  // +8 halves = +16 B for k8-15
    const int bG   = lane >> 3;
    const int bRow = (lane & 7) + ((bG >> 1) << 3);     // rows 0..15 of n16 pair
    const int bKB  = (bG & 1) * 16;

    float acc[4][4][4];
#pragma unroll
    for (int i = 0; i < 4; i++)
#pragma unroll
        for (int j = 0; j < 4; j++)
#pragma unroll
            for (int q = 0; q < 4; q++) acc[i][j][q] = 0.f;

    // chunk loader: tiles {Ah[,Am],Bh[,Bm]} x 128 rows x 64 B
    auto load_chunk = [&](int c, int stage) {
        const uint32_t stBase = sbase + stage * STAGE4;
#pragma unroll
        for (int i = 0; i < 8; i++) {
            const int t = i >> 1;                   // tile 0..3 (uniform per i)
            if (MODE == 1 && (t == 1 || t == 3)) continue;   // only Ah, Bh
            const int idx = tid + i * 256;          // 0..2047
            const int r = (idx >> 2) & 127;         // row 0..127
            const int s = idx & 3;                  // 16B segment 0..3
            const int rb = ((t < 2) ? mBase : nBase) + r;
            const int bound = (t < 2) ? M : N;
            const uint32_t dst = stBase + t * TILEB + r * TROWB + s * 16;
            const __half* src = srcs[t] + (size_t)rb * Dq + c * BKC + s * 8;
            cp16(dst, src, (rb < bound) ? 16u : 0u);
        }
        asm volatile("cp.async.commit_group;" ::: "memory");
    };

    load_chunk(c0, 0);

    for (int cc = 0; cc < NCHL; cc++) {
        if (cc + 1 < NCHL) {
            load_chunk(c0 + cc + 1, (cc + 1) & 1);
            asm volatile("cp.async.wait_group 1;" ::: "memory");
        } else {
            asm volatile("cp.async.wait_group 0;" ::: "memory");
        }
        __syncthreads();

        const uint32_t st = sbase + (cc & 1) * STAGE4;
        const uint32_t aH = st;
        const uint32_t aM = st + TILEB;
        const uint32_t bH = st + 2 * TILEB;
        const uint32_t bM = st + 3 * TILEB;

#pragma unroll
        for (int k16 = 0; k16 < BKC / 16; k16++) {
            const int kOff = k16 * 32;              // 16 halves = 32 B
            uint32_t bh[4][2], bm[4][2];
#pragma unroll
            for (int p = 0; p < 2; p++) {           // two n16 pairs cover nt 0..3
                const uint32_t bOff = (uint32_t)(wn + p * 16 + bRow) * TROWB + kOff + bKB;
                ldsm4(&bh[p * 2][0], bH + bOff);
                if (MODE == 3) ldsm4(&bm[p * 2][0], bM + bOff);
            }
#pragma unroll
            for (int mt = 0; mt < 4; mt++) {
                const uint32_t aOff = (uint32_t)(wm + mt * 16 + aRow) * TROWB + kOff + aKB;
                uint32_t ah[4], am[4];
                ldsm4(ah, aH + aOff);
                if (MODE == 3) ldsm4(am, aM + aOff);
#pragma unroll
                for (int nt = 0; nt < 4; nt++) {
                    mma16816(acc[mt][nt], ah, bh[nt]);
                    if (MODE == 3) {
                        mma16816(acc[mt][nt], ah, bm[nt]);
                        mma16816(acc[mt][nt], am, bh[nt]);
                    }
                }
            }
        }
        __syncthreads();
    }

    // epilogue: plain stores (split-K halves go to separate buffers)
#pragma unroll
    for (int mt = 0; mt < 4; mt++) {
        const int row0 = mBase + wm + mt * 16 + (lane >> 2);
#pragma unroll
        for (int nt = 0; nt < 4; nt++) {
            const int col0 = nBase + wn + nt * 8 + (lane & 3) * 2;
            if (col0 < N) {
                if (row0 < M)
                    *(float2*)&C[(size_t)row0 * N + col0] =
                        make_float2(acc[mt][nt][0], acc[mt][nt][1]);
                if (row0 + 8 < M)
                    *(float2*)&C[(size_t)(row0 + 8) * N + col0] =
                        make_float2(acc[mt][nt][2], acc[mt][nt][3]);
            }
        }
    }
}

// -- fused: split fp32 -> 2 fp16 limbs + inv L2 norm + zero class counters -------
__global__ __launch_bounds__(NTHR) void split_norm(
    const float* __restrict__ z, const float* __restrict__ W,
    __half* __restrict__ Ah, __half* __restrict__ Am, float* __restrict__ invn,
    int* __restrict__ cnt)
{
    const int r = blockIdx.x;   // support index: [0,Cq) = W, [Cq,Nsup) = z
    const float* src = (r < Cq) ? (W + (size_t)r * Dq) : (z + (size_t)(r - Cq) * Dq);
    const int tid = threadIdx.x;

    if (r == 0) for (int i = tid; i < Cq; i += NTHR) cnt[i] = 0;

    float ss = 0.f;
    const float4* src4 = (const float4*)src;
#pragma unroll
    for (int j = 0; j < Dq / (NTHR * 4); j++) {
        const int i4 = tid + j * NTHR;
        float4 x = src4[i4];
        const int i = i4 * 4;
        __half h0 = __float2half_rn(x.x), h1 = __float2half_rn(x.y);
        __half h2 = __float2half_rn(x.z), h3 = __float2half_rn(x.w);
        Ah[(size_t)r * Dq + i + 0] = h0; Ah[(size_t)r * Dq + i + 1] = h1;
        Ah[(size_t)r * Dq + i + 2] = h2; Ah[(size_t)r * Dq + i + 3] = h3;
        Am[(size_t)r * Dq + i + 0] = __float2half_rn(x.x - __half2float(h0));
        Am[(size_t)r * Dq + i + 1] = __float2half_rn(x.y - __half2float(h1));
        Am[(size_t)r * Dq + i + 2] = __float2half_rn(x.z - __half2float(h2));
        Am[(size_t)r * Dq + i + 3] = __float2half_rn(x.w - __half2float(h3));
        ss += x.x * x.x + x.y * x.y + x.z * x.z + x.w * x.w;
    }
    __shared__ float red[NTHR];
    red[tid] = ss; __syncthreads();
    for (int s = NTHR / 2; s > 0; s >>= 1) {
        if (tid < s) red[tid] += red[tid + s];
        __syncthreads();
    }
    if (tid == 0) invn[r] = 1.0f / fmaxf(sqrtf(red[0]), 1e-12f);
}

// -- warp-per-row: sum split-K partials, entropy + argmax + bucket scatter -------
// grid = Nsup/8 blocks of 8 warps; logits register-held (8 float4 per lane)
__global__ __launch_bounds__(NTHR) void row_entropy_scatter(
    const float* __restrict__ P0, const float* __restrict__ P1,
    int* __restrict__ cnt, float* __restrict__ bktE, int* __restrict__ bktI)
{
    const int row = blockIdx.x * 8 + (threadIdx.x >> 5);
    const int lane = threadIdx.x & 31;
    const float4* p0 = (const float4*)(P0 + (size_t)row * Cq);
    const float4* p1 = (const float4*)(P1 + (size_t)row * Cq);

    float4 v[8];
    float m = -FLT_MAX; int mi = 0x7fffffff;
#pragma unroll
    for (int j = 0; j < 8; j++) {
        const int i4 = lane + j * 32;
        if (i4 < 250) {
            float4 a = p0[i4], b = p1[i4];
            v[j] = make_float4(a.x + b.x, a.y + b.y, a.z + b.z, a.w + b.w);
            const int gi = i4 * 4;
            if (v[j].x > m) { m = v[j].x; mi = gi; }
            if (v[j].y > m) { m = v[j].y; mi = gi + 1; }
            if (v[j].z > m) { m = v[j].z; mi = gi + 2; }
            if (v[j].w > m) { m = v[j].w; mi = gi + 3; }
        } else {
            v[j] = make_float4(-FLT_MAX, -FLT_MAX, -FLT_MAX, -FLT_MAX);
        }
    }
    // butterfly max+argmax (lex order -> associative, all lanes converge)
#pragma unroll
    for (int o = 16; o > 0; o >>= 1) {
        float m2 = __shfl_xor_sync(0xffffffffu, m, o);
        int   i2 = __shfl_xor_sync(0xffffffffu, mi, o);
        if (m2 > m || (m2 == m && i2 < mi)) { m = m2; mi = i2; }
    }

    float s1 = 0.f, s2 = 0.f;
#pragma unroll
    for (int j = 0; j < 8; j++) {
        if (lane + j * 32 < 250) {
            float d0 = v[j].x - m, d1 = v[j].y - m, d2 = v[j].z - m, d3 = v[j].w - m;
            float e0 = expf(d0), e1 = expf(d1), e2 = expf(d2), e3 = expf(d3);
            s1 += e0 + e1 + e2 + e3;
            s2 += e0 * d0 + e1 * d1 + e2 * d2 + e3 * d3;
        }
    }
#pragma unroll
    for (int o = 16; o > 0; o >>= 1) {
        s1 += __shfl_xor_sync(0xffffffffu, s1, o);
        s2 += __shfl_xor_sync(0xffffffffu, s2, o);
    }

    if (lane == 0) {
        float e = logf(s1) - s2 / s1;
        int pos = atomicAdd(&cnt[mi], 1);
        bktE[(size_t)mi * BCAP + pos] = e;
        bktI[(size_t)mi * BCAP + pos] = row;
    }
}

// ---- per-class K smallest, warp-per-class, no mutation (ascending emit) --------
__global__ __launch_bounds__(NTHR) void select_topk(
    const int* __restrict__ cnt, const float* __restrict__ bktE,
    const int* __restrict__ bktI, const int* __restrict__ pK,
    int* __restrict__ selidx, int* __restrict__ selcnt)
{
    const int c = blockIdx.x * (NTHR / 32) + (threadIdx.x >> 5);
    if (c >= Cq) return;
    const int lane = threadIdx.x & 31;
    int K = *pK; if (K > KMAX) K = KMAX;
    const int n = cnt[c];
    const int take = (n < K) ? n : K;
    const float* E = bktE + (size_t)c * BCAP;
    const int*   I = bktI + (size_t)c * BCAP;

    float prevE = -FLT_MAX; int prevI = -1;
    for (int t = 0; t < take; t++) {
        // min over entries strictly greater (lex) than (prevE, prevI)
        float bv = FLT_MAX; int bk = 0x7fffffff;
        for (int i = lane; i < n; i += 32) {
            float v = E[i]; int key = I[i];
            bool gt_prev = (v > prevE) || (v == prevE && key > prevI);
            if (gt_prev && (v < bv || (v == bv && key < bk))) { bv = v; bk = key; }
        }
#pragma unroll
        for (int o = 16; o > 0; o >>= 1) {
            float v2 = __shfl_down_sync(0xffffffffu, bv, o);
            int   k2 = __shfl_down_sync(0xffffffffu, bk, o);
            if (v2 < bv || (v2 == bv && k2 < bk)) { bv = v2; bk = k2; }
        }
        bv = __shfl_sync(0xffffffffu, bv, 0);
        bk = __shfl_sync(0xffffffffu, bk, 0);
        if (lane == 0) selidx[c * KMAX + t] = bk;
        prevE = bv; prevI = bk;
    }
    if (lane == 0) selcnt[c] = take;
}

// ----- build normalized prototypes, emit fp16 high limb of weights^T ------------
__global__ __launch_bounds__(NTHR) void build_weights(
    const float* __restrict__ W, const float* __restrict__ z,
    const float* __restrict__ invn, const int* __restrict__ selidx,
    const int* __restrict__ selcnt, __half* __restrict__ Th)
{
    const int c = blockIdx.x;
    const int n = selcnt[c];
    const int tid = threadIdx.x;
    float acc[Dq / NTHR];
#pragma unroll
    for (int j = 0; j < Dq / NTHR; j++) acc[j] = 0.f;

    for (int t = 0; t < n; t++) {
        int idx = selidx[c * KMAX + t];
        float s = invn[idx];
        const float* row = (idx < Cq) ? (W + (size_t)idx * Dq) : (z + (size_t)(idx - Cq) * Dq);
#pragma unroll
        for (int j = 0; j < Dq / NTHR; j++) acc[j] += s * row[tid + j * NTHR];
    }

    float ss = 0.f;
#pragma unroll
    for (int j = 0; j < Dq / NTHR; j++) ss += acc[j] * acc[j];
    __shared__ float red[NTHR];
    red[tid] = ss; __syncthreads();
    for (int s = NTHR / 2; s > 0; s >>= 1) {
        if (tid < s) red[tid] += red[tid + s];
        __syncthreads();
    }
    const float inv = 1.0f / fmaxf(sqrtf(red[0]), 1e-12f);
#pragma unroll
    for (int j = 0; j < Dq / NTHR; j++)
        Th[(size_t)c * Dq + tid + j * NTHR] = __float2half_rn(acc[j] * inv);
}

// --------------------------------- launch ---------------------------------------
extern "C" void kernel_launch(void* const* d_in, const int* in_sizes, int n_in,
                              void* d_out, int out_size)
{
    const float* z = (const float*)d_in[0];
    const float* W = (const float*)d_in[1];
    const int* pK  = (const int*)d_in[2];
    float* out = (float*)d_out;

    float *P, *invn, *bktE;
    int *cnt, *bktI, *selidx, *selcnt;
    __half *Ah, *Am, *Th;
    cudaGetSymbolAddress((void**)&P, g_P);
    cudaGetSymbolAddress((void**)&invn, g_invn);
    cudaGetSymbolAddress((void**)&cnt, g_cnt);
    cudaGetSymbolAddress((void**)&bktE, g_bktE);
    cudaGetSymbolAddress((void**)&bktI, g_bktI);
    cudaGetSymbolAddress((void**)&selidx, g_selidx);
    cudaGetSymbolAddress((void**)&selcnt, g_selcnt);
    cudaGetSymbolAddress((void**)&Ah, g_Ah);
    cudaGetSymbolAddress((void**)&Am, g_Am);
    cudaGetSymbolAddress((void**)&Th, g_Th);

    cudaFuncSetAttribute((const void*)gemm_k<3, true>,
                         cudaFuncAttributeMaxDynamicSharedMemorySize, GSMEM);
    cudaFuncSetAttribute((const void*)gemm_k<1, false>,
                         cudaFuncAttributeMaxDynamicSharedMemorySize, GSMEM);

    // 0) limb split of [W; z], inverse norms, zero counters
    split_norm<<<Nsup, NTHR>>>(z, W, Ah, Am, invn, cnt);

    // 1) merged logits: split-K halves store to separate partial buffers
    gemm_k<3, true><<<dim3(8, 40, 2), 256, GSMEM>>>(Ah, Am, Ah, Am, P, Nsup, Cq);

    // 2) warp-per-row: sum partials, entropy + argmax + per-class bucket scatter
    row_entropy_scatter<<<Nsup / 8, NTHR>>>(P, P + PSZ, cnt, bktE, bktI);

    // 3) per-class selection (warp per class, read-only, ascending emit)
    select_topk<<<(Cq + (NTHR / 32) - 1) / (NTHR / 32), NTHR>>>(cnt, bktE, bktI, pK,
                                                               selidx, selcnt);

    // 4) prototypes (fp16 high limb only)
    build_weights<<<Cq, NTHR>>>(W, z, invn, selidx, selcnt, Th);

    // 5) out = z @ weights   (single-pair fp16)
    gemm_k<1, false><<<dim3(8, 32), 256, GSMEM>>>(Ah + (size_t)Cq * Dq, Am + (size_t)Cq * Dq,
                                                  Th, Th, out, Bq, Cq);
}